// round 9
// baseline (speedup 1.0000x reference)
#include <cuda_runtime.h>
#include <cstdint>

#define NN   4096
#define NE   32768
#define ET   (NE + NN)        // edges + self loops = 36864
#define F_IN 128
#define HEADS 8
#define HID  512
#define D1   (HEADS * HID)    // 4096
#define SK   4                // fc1 split-K factor

// ---------------- scratch (device globals; no allocation allowed) ----------
__device__ float g_h1[(size_t)NN * D1];     // 64 MB
__device__ float g_out1[(size_t)NN * D1];   // 64 MB
__device__ float g_h2[NN * HID];            // 8 MB
__device__ float g_out2[NN * HID];          // 8 MB
__device__ float g_wa1[F_IN * 16];          // W1 @ [a_src;a_dst] projections
__device__ float g_as1[NN * HEADS], g_ad1[NN * HEADS];
__device__ float g_as2[NN], g_ad2[NN];
__device__ int   g_deg[NN], g_cur[NN], g_off[NN + 1];
__device__ int   g_esrc[ET];
__device__ int   g_is64;
__device__ float g_g1[512 * 512], g_g2[512 * 128];
__device__ float g_skp[SK * 512 * 512];     // fc1 split-K partials (4 MB)

// ---------------- helpers ---------------------------------------------------
__device__ __forceinline__ float warpSum(float v) {
    #pragma unroll
    for (int o = 16; o; o >>= 1) v += __shfl_xor_sync(0xffffffffu, v, o);
    return v;
}
__device__ __forceinline__ float warpMax(float v) {
    #pragma unroll
    for (int o = 16; o; o >>= 1) v = fmaxf(v, __shfl_xor_sync(0xffffffffu, v, o));
    return v;
}
__device__ __forceinline__ uint32_t f2tf32(float f) {
    uint32_t o;
    asm("cvt.rna.tf32.f32 %0, %1;" : "=r"(o) : "f"(f));
    return o;
}
__device__ __forceinline__ float lrelu(float v) {
    return v > 0.f ? v : 0.2f * v;
}
__device__ __forceinline__ int eload(const int* ei, int pos) {
    return g_is64 ? ei[2 * pos] : ei[pos];
}
__device__ __forceinline__ int esrc_of(const int* ei, int e) {
    return (e < NE) ? eload(ei, e) : (e - NE);
}
__device__ __forceinline__ int edst_of(const int* ei, int e) {
    return (e < NE) ? eload(ei, NE + e) : (e - NE);
}

// ---------------- dtype sniff + CSR build ----------------------------------
__global__ void detect_init_kernel(const int* __restrict__ ei) {
    int i = blockIdx.x * blockDim.x + threadIdx.x;
    if (i == 0) {
        int all0 = 1;
        for (int k = 1; k < 64; k += 2) all0 &= (ei[k] == 0);
        g_is64 = all0;
    }
    if (i < NN) { g_deg[i] = 0; g_cur[i] = 0; }
}

__global__ void count_kernel(const int* __restrict__ ei) {
    int e = blockIdx.x * blockDim.x + threadIdx.x;
    if (e >= ET) return;
    atomicAdd(&g_deg[edst_of(ei, e)], 1);
}

__global__ void scan_kernel() {
    __shared__ int ws[32];
    int t = threadIdx.x, lane = t & 31, wid = t >> 5;
    int a0 = g_deg[4 * t + 0], a1 = g_deg[4 * t + 1];
    int a2 = g_deg[4 * t + 2], a3 = g_deg[4 * t + 3];
    int tsum = a0 + a1 + a2 + a3;
    int x = tsum;
    #pragma unroll
    for (int o = 1; o < 32; o <<= 1) {
        int y = __shfl_up_sync(0xffffffffu, x, o);
        if (lane >= o) x += y;
    }
    if (lane == 31) ws[wid] = x;
    __syncthreads();
    if (wid == 0) {
        int y = ws[lane];
        #pragma unroll
        for (int o = 1; o < 32; o <<= 1) {
            int z = __shfl_up_sync(0xffffffffu, y, o);
            if (lane >= o) y += z;
        }
        ws[lane] = y;
    }
    __syncthreads();
    int base = (wid ? ws[wid - 1] : 0) + (x - tsum);
    g_off[4 * t + 0] = base;
    g_off[4 * t + 1] = base + a0;
    g_off[4 * t + 2] = base + a0 + a1;
    g_off[4 * t + 3] = base + a0 + a1 + a2;
    if (t == 1023) g_off[NN] = base + tsum;
}

__global__ void fill_kernel(const int* __restrict__ ei) {
    int e = blockIdx.x * blockDim.x + threadIdx.x;
    if (e >= ET) return;
    int s = esrc_of(ei, e), d = edst_of(ei, e);
    int p = g_off[d] + atomicAdd(&g_cur[d], 1);
    g_esrc[p] = s;
}

// ---------------- TF32 tensor-core GEMM (mma.sync, double-buffered) ----------
// A[M,K] rm, B[K,N] rm, C[M,N]. Requires M%BM==0, N%BN==0, K%32==0.
template<int BM, int BN, int WM, int WN>
__global__ __launch_bounds__((BM / WM) * (BN / WN) * 32)
void tf32gemm(const float* __restrict__ A, const float* __restrict__ B,
              const float* __restrict__ bias, float* __restrict__ C,
              int M, int N, int K, int relu)
{
    constexpr int BK = 32;
    constexpr int WARPS = (BM / WM) * (BN / WN);
    constexpr int THREADS = WARPS * 32;
    constexpr int MF = WM / 16, NF = WN / 8;
    constexpr int AST = BK + 4;
    constexpr int BST = BN + 4;
    constexpr int ALD = (BM * BK) / (4 * THREADS);
    constexpr int BLD = (BK * BN) / (4 * THREADS);
    constexpr int STAGE = BM * AST + BK * BST;

    extern __shared__ uint32_t smem_dyn[];
    const int tid = threadIdx.x;
    const int wid = tid >> 5, lane = tid & 31;
    const int wm = wid / (BN / WN), wn = wid % (BN / WN);
    const int g = lane >> 2, tg = lane & 3;
    const int row0 = blockIdx.y * BM, col0 = blockIdx.x * BN;

    float acc[MF][NF][4];
    #pragma unroll
    for (int i = 0; i < MF; i++)
        #pragma unroll
        for (int j = 0; j < NF; j++)
            #pragma unroll
            for (int q = 0; q < 4; q++) acc[i][j][q] = 0.f;

    float4 pa[ALD], pb[BLD];
    auto ldAB = [&](int k0) {
        #pragma unroll
        for (int j = 0; j < ALD; j++) {
            int fid = tid + j * THREADS;
            int r = fid / (BK / 4), c4 = fid % (BK / 4);
            pa[j] = *reinterpret_cast<const float4*>(A + (size_t)(row0 + r) * K + k0 + c4 * 4);
        }
        #pragma unroll
        for (int j = 0; j < BLD; j++) {
            int fid = tid + j * THREADS;
            int r = fid / (BN / 4), c4 = fid % (BN / 4);
            pb[j] = *reinterpret_cast<const float4*>(B + (size_t)(k0 + r) * N + col0 + c4 * 4);
        }
    };
    auto stash = [&](int buf) {
        uint32_t* As = smem_dyn + buf * STAGE;
        uint32_t* Bs = As + BM * AST;
        #pragma unroll
        for (int j = 0; j < ALD; j++) {
            int fid = tid + j * THREADS;
            int r = fid / (BK / 4), c4 = fid % (BK / 4);
            uint4 v;
            v.x = f2tf32(pa[j].x); v.y = f2tf32(pa[j].y);
            v.z = f2tf32(pa[j].z); v.w = f2tf32(pa[j].w);
            *reinterpret_cast<uint4*>(&As[r * AST + c4 * 4]) = v;
        }
        #pragma unroll
        for (int j = 0; j < BLD; j++) {
            int fid = tid + j * THREADS;
            int r = fid / (BN / 4), c4 = fid % (BN / 4);
            uint4 v;
            v.x = f2tf32(pb[j].x); v.y = f2tf32(pb[j].y);
            v.z = f2tf32(pb[j].z); v.w = f2tf32(pb[j].w);
            *reinterpret_cast<uint4*>(&Bs[r * BST + c4 * 4]) = v;
        }
    };

    ldAB(0);
    stash(0);
    __syncthreads();

    const int niter = K / BK;
    for (int it = 0; it < niter; ++it) {
        const int cur = it & 1;
        if (it + 1 < niter) ldAB((it + 1) * BK);
        const uint32_t* As = smem_dyn + cur * STAGE;
        const uint32_t* Bs = As + BM * AST;
        #pragma unroll
        for (int kk = 0; kk < 4; kk++) {
            uint32_t af[MF][4], bf[NF][2];
            #pragma unroll
            for (int mf = 0; mf < MF; mf++) {
                int r = wm * WM + mf * 16;
                af[mf][0] = As[(r + g    ) * AST + kk * 8 + tg    ];
                af[mf][1] = As[(r + g + 8) * AST + kk * 8 + tg    ];
                af[mf][2] = As[(r + g    ) * AST + kk * 8 + tg + 4];
                af[mf][3] = As[(r + g + 8) * AST + kk * 8 + tg + 4];
            }
            #pragma unroll
            for (int nf = 0; nf < NF; nf++) {
                int c = wn * WN + nf * 8 + g;
                bf[nf][0] = Bs[(kk * 8 + tg    ) * BST + c];
                bf[nf][1] = Bs[(kk * 8 + tg + 4) * BST + c];
            }
            #pragma unroll
            for (int mf = 0; mf < MF; mf++)
                #pragma unroll
                for (int nf = 0; nf < NF; nf++)
                    asm volatile(
                        "mma.sync.aligned.m16n8k8.row.col.f32.tf32.tf32.f32 "
                        "{%0,%1,%2,%3},{%4,%5,%6,%7},{%8,%9},{%0,%1,%2,%3};\n"
                        : "+f"(acc[mf][nf][0]), "+f"(acc[mf][nf][1]),
                          "+f"(acc[mf][nf][2]), "+f"(acc[mf][nf][3])
                        : "r"(af[mf][0]), "r"(af[mf][1]),
                          "r"(af[mf][2]), "r"(af[mf][3]),
                          "r"(bf[nf][0]), "r"(bf[nf][1]));
        }
        if (it + 1 < niter) {
            stash(1 - cur);
            __syncthreads();
        }
    }
    #pragma unroll
    for (int mf = 0; mf < MF; mf++) {
        int r = row0 + wm * WM + mf * 16 + g;
        #pragma unroll
        for (int nf = 0; nf < NF; nf++) {
            int c = col0 + wn * WN + nf * 8 + tg * 2;
            float b0v = bias ? bias[c] : 0.f;
            float b1v = bias ? bias[c + 1] : 0.f;
            float v0 = acc[mf][nf][0] + b0v, v1 = acc[mf][nf][1] + b1v;
            float v2 = acc[mf][nf][2] + b0v, v3 = acc[mf][nf][3] + b1v;
            if (relu) {
                v0 = fmaxf(v0, 0.f); v1 = fmaxf(v1, 0.f);
                v2 = fmaxf(v2, 0.f); v3 = fmaxf(v3, 0.f);
            }
            *reinterpret_cast<float2*>(C + (size_t)r * N + c) = make_float2(v0, v1);
            *reinterpret_cast<float2*>(C + (size_t)(r + 8) * N + c) = make_float2(v2, v3);
        }
    }
}

// ---------------- split-K variant: partials to Cp[z][M*N], no bias/relu ------
template<int BM, int BN, int WM, int WN, int SPLITK>
__global__ __launch_bounds__((BM / WM) * (BN / WN) * 32)
void tf32gemm_sk(const float* __restrict__ A, const float* __restrict__ B,
                 float* __restrict__ Cp, int M, int N, int K)
{
    constexpr int BK = 32;
    constexpr int WARPS = (BM / WM) * (BN / WN);
    constexpr int THREADS = WARPS * 32;
    constexpr int MF = WM / 16, NF = WN / 8;
    constexpr int AST = BK + 4;
    constexpr int BST = BN + 4;
    constexpr int ALD = (BM * BK) / (4 * THREADS);
    constexpr int BLD = (BK * BN) / (4 * THREADS);
    constexpr int STAGE = BM * AST + BK * BST;

    extern __shared__ uint32_t smem_dyn[];
    const int tid = threadIdx.x;
    const int wid = tid >> 5, lane = tid & 31;
    const int wm = wid / (BN / WN), wn = wid % (BN / WN);
    const int g = lane >> 2, tg = lane & 3;
    const int row0 = blockIdx.y * BM, col0 = blockIdx.x * BN;
    const int kbase = blockIdx.z * (K / SPLITK);
    float* C = Cp + (size_t)blockIdx.z * M * N;

    float acc[MF][NF][4];
    #pragma unroll
    for (int i = 0; i < MF; i++)
        #pragma unroll
        for (int j = 0; j < NF; j++)
            #pragma unroll
            for (int q = 0; q < 4; q++) acc[i][j][q] = 0.f;

    float4 pa[ALD], pb[BLD];
    auto ldAB = [&](int k0) {
        #pragma unroll
        for (int j = 0; j < ALD; j++) {
            int fid = tid + j * THREADS;
            int r = fid / (BK / 4), c4 = fid % (BK / 4);
            pa[j] = *reinterpret_cast<const float4*>(A + (size_t)(row0 + r) * K + k0 + c4 * 4);
        }
        #pragma unroll
        for (int j = 0; j < BLD; j++) {
            int fid = tid + j * THREADS;
            int r = fid / (BN / 4), c4 = fid % (BN / 4);
            pb[j] = *reinterpret_cast<const float4*>(B + (size_t)(k0 + r) * N + col0 + c4 * 4);
        }
    };
    auto stash = [&](int buf) {
        uint32_t* As = smem_dyn + buf * STAGE;
        uint32_t* Bs = As + BM * AST;
        #pragma unroll
        for (int j = 0; j < ALD; j++) {
            int fid = tid + j * THREADS;
            int r = fid / (BK / 4), c4 = fid % (BK / 4);
            uint4 v;
            v.x = f2tf32(pa[j].x); v.y = f2tf32(pa[j].y);
            v.z = f2tf32(pa[j].z); v.w = f2tf32(pa[j].w);
            *reinterpret_cast<uint4*>(&As[r * AST + c4 * 4]) = v;
        }
        #pragma unroll
        for (int j = 0; j < BLD; j++) {
            int fid = tid + j * THREADS;
            int r = fid / (BN / 4), c4 = fid % (BN / 4);
            uint4 v;
            v.x = f2tf32(pb[j].x); v.y = f2tf32(pb[j].y);
            v.z = f2tf32(pb[j].z); v.w = f2tf32(pb[j].w);
            *reinterpret_cast<uint4*>(&Bs[r * BST + c4 * 4]) = v;
        }
    };

    ldAB(kbase);
    stash(0);
    __syncthreads();

    const int niter = (K / SPLITK) / BK;
    for (int it = 0; it < niter; ++it) {
        const int cur = it & 1;
        if (it + 1 < niter) ldAB(kbase + (it + 1) * BK);
        const uint32_t* As = smem_dyn + cur * STAGE;
        const uint32_t* Bs = As + BM * AST;
        #pragma unroll
        for (int kk = 0; kk < 4; kk++) {
            uint32_t af[MF][4], bf[NF][2];
            #pragma unroll
            for (int mf = 0; mf < MF; mf++) {
                int r = wm * WM + mf * 16;
                af[mf][0] = As[(r + g    ) * AST + kk * 8 + tg    ];
                af[mf][1] = As[(r + g + 8) * AST + kk * 8 + tg    ];
                af[mf][2] = As[(r + g    ) * AST + kk * 8 + tg + 4];
                af[mf][3] = As[(r + g + 8) * AST + kk * 8 + tg + 4];
            }
            #pragma unroll
            for (int nf = 0; nf < NF; nf++) {
                int c = wn * WN + nf * 8 + g;
                bf[nf][0] = Bs[(kk * 8 + tg    ) * BST + c];
                bf[nf][1] = Bs[(kk * 8 + tg + 4) * BST + c];
            }
            #pragma unroll
            for (int mf = 0; mf < MF; mf++)
                #pragma unroll
                for (int nf = 0; nf < NF; nf++)
                    asm volatile(
                        "mma.sync.aligned.m16n8k8.row.col.f32.tf32.tf32.f32 "
                        "{%0,%1,%2,%3},{%4,%5,%6,%7},{%8,%9},{%0,%1,%2,%3};\n"
                        : "+f"(acc[mf][nf][0]), "+f"(acc[mf][nf][1]),
                          "+f"(acc[mf][nf][2]), "+f"(acc[mf][nf][3])
                        : "r"(af[mf][0]), "r"(af[mf][1]),
                          "r"(af[mf][2]), "r"(af[mf][3]),
                          "r"(bf[nf][0]), "r"(bf[nf][1]));
        }
        if (it + 1 < niter) {
            stash(1 - cur);
            __syncthreads();
        }
    }
    #pragma unroll
    for (int mf = 0; mf < MF; mf++) {
        int r = row0 + wm * WM + mf * 16 + g;
        #pragma unroll
        for (int nf = 0; nf < NF; nf++) {
            int c = col0 + wn * WN + nf * 8 + tg * 2;
            *reinterpret_cast<float2*>(C + (size_t)r * N + c) =
                make_float2(acc[mf][nf][0], acc[mf][nf][1]);
            *reinterpret_cast<float2*>(C + (size_t)(r + 8) * N + c) =
                make_float2(acc[mf][nf][2], acc[mf][nf][3]);
        }
    }
}

// reduce split-K partials + bias + relu (float4)
__global__ void sk_reduce_kernel(const float* __restrict__ bias,
                                 float* __restrict__ out, int MN, int N) {
    int i = blockIdx.x * blockDim.x + threadIdx.x;   // float4 index
    if (i * 4 >= MN) return;
    const float4* p = reinterpret_cast<const float4*>(g_skp);
    int q = MN / 4;
    float4 a = p[i], b = p[i + q], c = p[i + 2 * q], d = p[i + 3 * q];
    float4 bv = *reinterpret_cast<const float4*>(bias + (i * 4) % N);
    float4 o;
    o.x = fmaxf(a.x + b.x + c.x + d.x + bv.x, 0.f);
    o.y = fmaxf(a.y + b.y + c.y + d.y + bv.y, 0.f);
    o.z = fmaxf(a.z + b.z + c.z + d.z + bv.z, 0.f);
    o.w = fmaxf(a.w + b.w + c.w + d.w + bv.w, 0.f);
    reinterpret_cast<float4*>(out)[i] = o;
}

// ---------------- fp32 tiled SGEMM (tail GEMM only) --------------------------
template<int BM, int BN, int BK, int TM, int TN>
__global__ __launch_bounds__((BM / TM) * (BN / TN))
void sgemm(const float* __restrict__ A, const float* __restrict__ B,
           const float* __restrict__ bias, float* __restrict__ C,
           int M, int N, int K, int relu)
{
    constexpr int THREADS = (BM / TM) * (BN / TN);
    __shared__ float As[BK][BM];
    __shared__ float Bs[BK][BN];
    const int tid = threadIdx.x;
    const int row0 = blockIdx.y * BM, col0 = blockIdx.x * BN;
    const int tr = (tid / (BN / TN)) * TM;
    const int tc = (tid % (BN / TN)) * TN;
    const bool vb = (N % 4) == 0;

    float acc[TM][TN];
    #pragma unroll
    for (int i = 0; i < TM; i++)
        #pragma unroll
        for (int j = 0; j < TN; j++) acc[i][j] = 0.f;

    for (int k0 = 0; k0 < K; k0 += BK) {
        #pragma unroll 4
        for (int i = tid * 4; i < BM * BK; i += THREADS * 4) {
            int r = i / BK, c = i % BK;
            int gr = row0 + r, gc = k0 + c;
            float4 v = make_float4(0.f, 0.f, 0.f, 0.f);
            if (gr < M) v = *reinterpret_cast<const float4*>(A + (size_t)gr * K + gc);
            As[c + 0][r] = v.x; As[c + 1][r] = v.y;
            As[c + 2][r] = v.z; As[c + 3][r] = v.w;
        }
        #pragma unroll 4
        for (int i = tid * 4; i < BK * BN; i += THREADS * 4) {
            int r = i / BN, c = i % BN;
            int gr = k0 + r, gc = col0 + c;
            float vv0 = 0.f, vv1 = 0.f, vv2 = 0.f, vv3 = 0.f;
            if (vb && gc + 3 < N) {
                float4 v = *reinterpret_cast<const float4*>(B + (size_t)gr * N + gc);
                vv0 = v.x; vv1 = v.y; vv2 = v.z; vv3 = v.w;
            } else {
                if (gc + 0 < N) vv0 = B[(size_t)gr * N + gc + 0];
                if (gc + 1 < N) vv1 = B[(size_t)gr * N + gc + 1];
                if (gc + 2 < N) vv2 = B[(size_t)gr * N + gc + 2];
                if (gc + 3 < N) vv3 = B[(size_t)gr * N + gc + 3];
            }
            Bs[r][c + 0] = vv0; Bs[r][c + 1] = vv1;
            Bs[r][c + 2] = vv2; Bs[r][c + 3] = vv3;
        }
        __syncthreads();
        #pragma unroll
        for (int kk = 0; kk < BK; kk++) {
            float ar[TM], br[TN];
            #pragma unroll
            for (int i = 0; i < TM; i++) ar[i] = As[kk][tr + i];
            #pragma unroll
            for (int j = 0; j < TN; j++) br[j] = Bs[kk][tc + j];
            #pragma unroll
            for (int i = 0; i < TM; i++)
                #pragma unroll
                for (int j = 0; j < TN; j++) acc[i][j] += ar[i] * br[j];
        }
        __syncthreads();
    }
    #pragma unroll
    for (int i = 0; i < TM; i++) {
        int r = row0 + tr + i;
        if (r >= M) continue;
        #pragma unroll
        for (int j = 0; j < TN; j++) {
            int c = col0 + tc + j;
            if (c >= N) continue;
            float v = acc[i][j] + (bias ? bias[c] : 0.f);
            if (relu) v = fmaxf(v, 0.f);
            C[(size_t)r * N + c] = v;
        }
    }
}

// ---------------- GAT layer 1 -------------------------------------------------
__global__ void prep_wa1_kernel(const float* __restrict__ W1,
                                const float* __restrict__ a1s,
                                const float* __restrict__ a1d) {
    int f = blockIdx.x;
    int w = threadIdx.x >> 5, lane = threadIdx.x & 31;   // 16 warps
    int h = w & 7;
    const float* a = (w < 8) ? a1s : a1d;
    float s = 0.f;
    for (int c = lane; c < HID; c += 32)
        s += W1[(size_t)f * D1 + h * HID + c] * a[h * HID + c];
    s = warpSum(s);
    if (lane == 0) g_wa1[f * 16 + w] = s;
}

__global__ void alpha1_fast_kernel(const float* __restrict__ x) {
    int n = blockIdx.x * 8 + (threadIdx.x >> 5);
    int lane = threadIdx.x & 31;
    float xv[4];
    #pragma unroll
    for (int j = 0; j < 4; j++) xv[j] = x[(size_t)n * F_IN + lane + 32 * j];
    #pragma unroll
    for (int o = 0; o < 16; o++) {
        float s = 0.f;
        #pragma unroll
        for (int j = 0; j < 4; j++) s += xv[j] * g_wa1[(lane + 32 * j) * 16 + o];
        s = warpSum(s);
        if (lane == 0) {
            if (o < 8) g_as1[n * 8 + o] = s;
            else       g_ad1[n * 8 + (o - 8)] = s;
        }
    }
}

// fused leaky-relu logits + segment-softmax + weighted gather-aggregate (L1)
#define CH1 128
__global__ __launch_bounds__(256)
void norm_agg1_kernel(const float* __restrict__ b1) {
    __shared__ float sm[HEADS], sinv[HEADS], sadn[HEADS];
    __shared__ float sal[CH1 * HEADS];
    __shared__ int   ssrc[CH1];
    int n = blockIdx.x;
    int t = threadIdx.x, w = t >> 5, lane = t & 31;
    int beg = g_off[n], end = g_off[n + 1];

    float adn = g_ad1[n * HEADS + w];
    if (lane == 0) sadn[w] = adn;
    float m = -3.4e38f;
    for (int i = beg + lane; i < end; i += 32)
        m = fmaxf(m, lrelu(g_as1[g_esrc[i] * HEADS + w] + adn));
    m = warpMax(m);
    float s = 0.f;
    for (int i = beg + lane; i < end; i += 32)
        s += expf(lrelu(g_as1[g_esrc[i] * HEADS + w] + adn) - m);
    s = warpSum(s);
    if (lane == 0) { sm[w] = m; sinv[w] = 1.f / s; }
    __syncthreads();

    int c0 = t * 16;
    int head = c0 >> 9;
    float acc[16];
    #pragma unroll
    for (int j = 0; j < 16; j++) acc[j] = 0.f;

    for (int cs = beg; cs < end; cs += CH1) {
        int cnt = min(end - cs, CH1);
        for (int j = t; j < cnt; j += 256) ssrc[j] = g_esrc[cs + j];
        __syncthreads();
        for (int j = t; j < cnt * HEADS; j += 256) {
            int i = j >> 3, h = j & 7;
            float v = lrelu(g_as1[ssrc[i] * HEADS + h] + sadn[h]);
            sal[j] = expf(v - sm[h]) * sinv[h];
        }
        __syncthreads();
        #pragma unroll 2
        for (int i = 0; i < cnt; i++) {
            float al = sal[i * HEADS + head];
            const float4* hs = reinterpret_cast<const float4*>(
                g_h1 + (size_t)ssrc[i] * D1 + c0);
            #pragma unroll
            for (int j = 0; j < 4; j++) {
                float4 v = hs[j];
                acc[4 * j + 0] += v.x * al; acc[4 * j + 1] += v.y * al;
                acc[4 * j + 2] += v.z * al; acc[4 * j + 3] += v.w * al;
            }
        }
        __syncthreads();
    }
    float* o = g_out1 + (size_t)n * D1 + c0;
    #pragma unroll
    for (int j = 0; j < 16; j++)
        o[j] = fmaxf(acc[j] + b1[c0 + j], 0.f);
}

// ---------------- GAT layer 2 -------------------------------------------------
__global__ void alpha2_kernel(const float* __restrict__ asrc,
                              const float* __restrict__ adst) {
    int n = blockIdx.x * 8 + (threadIdx.x >> 5);
    int lane = threadIdx.x & 31;
    const float* hrow = g_h2 + (size_t)n * HID;
    float s1 = 0.f, s2 = 0.f;
    for (int c = lane; c < HID; c += 32) {
        float v = hrow[c];
        s1 += v * asrc[c];
        s2 += v * adst[c];
    }
    s1 = warpSum(s1); s2 = warpSum(s2);
    if (lane == 0) { g_as2[n] = s1; g_ad2[n] = s2; }
}

#define CH2 256
__global__ __launch_bounds__(128)
void norm_agg2_kernel(const float* __restrict__ b2) {
    __shared__ float sred[4];
    __shared__ float sal[CH2];
    __shared__ int   ssrc[CH2];
    int n = blockIdx.x;
    int t = threadIdx.x, w = t >> 5, lane = t & 31;
    int beg = g_off[n], end = g_off[n + 1];
    float adn = g_ad2[n];

    float m = -3.4e38f;
    for (int i = beg + t; i < end; i += 128)
        m = fmaxf(m, lrelu(g_as2[g_esrc[i]] + adn));
    m = warpMax(m);
    if (lane == 0) sred[w] = m;
    __syncthreads();
    m = fmaxf(fmaxf(sred[0], sred[1]), fmaxf(sred[2], sred[3]));
    __syncthreads();
    float s = 0.f;
    for (int i = beg + t; i < end; i += 128)
        s += expf(lrelu(g_as2[g_esrc[i]] + adn) - m);
    s = warpSum(s);
    if (lane == 0) sred[w] = s;
    __syncthreads();
    float inv = 1.f / (sred[0] + sred[1] + sred[2] + sred[3]);

    int c0 = t * 4;
    float a0 = 0.f, a1 = 0.f, a2 = 0.f, a3 = 0.f;
    for (int cs = beg; cs < end; cs += CH2) {
        int cnt = min(end - cs, CH2);
        __syncthreads();
        for (int j = t; j < cnt; j += 128) {
            int sc = g_esrc[cs + j];
            ssrc[j] = sc;
            sal[j] = expf(lrelu(g_as2[sc] + adn) - m) * inv;
        }
        __syncthreads();
        #pragma unroll 2
        for (int i = 0; i < cnt; i++) {
            float al = sal[i];
            float4 v = *reinterpret_cast<const float4*>(
                g_h2 + (size_t)ssrc[i] * HID + c0);
            a0 += v.x * al; a1 += v.y * al; a2 += v.z * al; a3 += v.w * al;
        }
    }
    float* o = g_out2 + (size_t)n * HID + c0;
    o[0] = fmaxf(a0 + b2[c0 + 0], 0.f);
    o[1] = fmaxf(a1 + b2[c0 + 1], 0.f);
    o[2] = fmaxf(a2 + b2[c0 + 2], 0.f);
    o[3] = fmaxf(a3 + b2[c0 + 3], 0.f);
}

// ---------------- launch -----------------------------------------------------
static inline int smem_bytes(int BM, int BN) {
    return 2 * (BM * 36 + 32 * (BN + 4)) * 4;
}

extern "C" void kernel_launch(void* const* d_in, const int* in_sizes, int n_in,
                              void* d_out, int out_size) {
    const float* x      = (const float*)d_in[0];
    const int*   ei     = (const int*)d_in[1];
    const float* W1     = (const float*)d_in[3];
    const float* a_src1 = (const float*)d_in[4];
    const float* a_dst1 = (const float*)d_in[5];
    const float* b1     = (const float*)d_in[6];
    const float* W2     = (const float*)d_in[7];
    const float* a_src2 = (const float*)d_in[8];
    const float* a_dst2 = (const float*)d_in[9];
    const float* b2     = (const float*)d_in[10];
    const float* fc1w   = (const float*)d_in[11];
    const float* fc1b   = (const float*)d_in[12];
    const float* fc2w   = (const float*)d_in[13];
    const float* fc2b   = (const float*)d_in[14];
    const float* fc3w   = (const float*)d_in[15];
    const float* fc3b   = (const float*)d_in[16];
    float* out = (float*)d_out;

    float *h1, *o1, *h2, *o2, *gg1, *gg2, *skp;
    cudaGetSymbolAddress((void**)&h1,  g_h1);
    cudaGetSymbolAddress((void**)&o1,  g_out1);
    cudaGetSymbolAddress((void**)&h2,  g_h2);
    cudaGetSymbolAddress((void**)&o2,  g_out2);
    cudaGetSymbolAddress((void**)&gg1, g_g1);
    cudaGetSymbolAddress((void**)&gg2, g_g2);
    cudaGetSymbolAddress((void**)&skp, g_skp);

    const int SM_BIG  = smem_bytes(128, 128);   // 70656 B
    const int SM_MED  = smem_bytes(128, 64);    // 54272 B
    const int SM_SMALL = smem_bytes(64, 64);    // 35840 B
    cudaFuncSetAttribute(tf32gemm<128, 128, 64, 32>,
                         cudaFuncAttributeMaxDynamicSharedMemorySize, SM_BIG);
    cudaFuncSetAttribute(tf32gemm<128, 64, 64, 32>,
                         cudaFuncAttributeMaxDynamicSharedMemorySize, SM_MED);
    cudaFuncSetAttribute(tf32gemm<64, 64, 32, 32>,
                         cudaFuncAttributeMaxDynamicSharedMemorySize, SM_SMALL);
    cudaFuncSetAttribute(tf32gemm_sk<64, 64, 32, 32, SK>,
                         cudaFuncAttributeMaxDynamicSharedMemorySize, SM_SMALL);

    // stream fork: s1 = CSR build, s2 = alpha1 projection, main = GEMM1
    cudaStream_t s1, s2;
    cudaStreamCreate(&s1);
    cudaStreamCreate(&s2);
    cudaEvent_t eFork, eCsr, eAl;
    cudaEventCreateWithFlags(&eFork, cudaEventDisableTiming);
    cudaEventCreateWithFlags(&eCsr,  cudaEventDisableTiming);
    cudaEventCreateWithFlags(&eAl,   cudaEventDisableTiming);

    cudaEventRecord(eFork, 0);
    cudaStreamWaitEvent(s1, eFork, 0);
    cudaStreamWaitEvent(s2, eFork, 0);

    // s1: edge dtype + CSR
    detect_init_kernel<<<(NN + 255) / 256, 256, 0, s1>>>(ei);
    count_kernel<<<(ET + 255) / 256, 256, 0, s1>>>(ei);
    scan_kernel<<<1, 1024, 0, s1>>>();
    fill_kernel<<<(ET + 255) / 256, 256, 0, s1>>>(ei);
    cudaEventRecord(eCsr, s1);

    // s2: alpha1 projection
    prep_wa1_kernel<<<F_IN, 512, 0, s2>>>(W1, a_src1, a_dst1);
    alpha1_fast_kernel<<<NN / 8, 256, 0, s2>>>(x);
    cudaEventRecord(eAl, s2);

    // main: GAT layer 1 GEMM h1 = x @ W1
    tf32gemm<128, 128, 64, 32><<<dim3(D1 / 128, NN / 128), 256, SM_BIG>>>(
        x, W1, nullptr, h1, NN, D1, F_IN, 0);

    // join
    cudaStreamWaitEvent(0, eCsr, 0);
    cudaStreamWaitEvent(0, eAl, 0);
    norm_agg1_kernel<<<NN, 256>>>(b1);

    // GAT layer 2: h2 = out1 @ W2 (128x64 tiles, 2 CTAs/SM, 256 CTAs)
    tf32gemm<128, 64, 64, 32><<<dim3(HID / 64, NN / 128), 128, SM_MED>>>(
        o1, W2, nullptr, h2, NN, HID, D1, 0);
    alpha2_kernel<<<NN / 8, 256>>>(a_src2, a_dst2);
    norm_agg2_kernel<<<NN, 128>>>(b2);

    // MLP head: fc1 split-K=4 (256 CTAs) + reduce
    tf32gemm_sk<64, 64, 32, 32, SK><<<dim3(8, 8, SK), 128, SM_SMALL>>>(
        o2, fc1w, skp, 512, 512, D1);
    sk_reduce_kernel<<<(512 * 512 / 4 + 255) / 256, 256>>>(fc1b, gg1, 512 * 512, 512);

    tf32gemm<64, 64, 32, 32><<<dim3(128 / 64, 512 / 64), 128, SM_SMALL>>>(
        gg1, fc2w, fc2b, gg2, 512, 128, 512, 1);
    sgemm<64, 64, 16, 4, 4><<<dim3(1, 512 / 64), 256>>>(
        gg2, fc3w, fc3b, out, 512, 10, 128, 0);

    cudaEventDestroy(eFork);
    cudaEventDestroy(eCsr);
    cudaEventDestroy(eAl);
    cudaStreamDestroy(s1);
    cudaStreamDestroy(s2);
}

// round 12
// speedup vs baseline: 1.4588x; 1.4588x over previous
#include <cuda_runtime.h>
#include <cstdint>

#define NN   4096
#define NE   32768
#define ET   (NE + NN)        // edges + self loops = 36864
#define F_IN 128
#define HEADS 8
#define HID  512
#define D1   (HEADS * HID)    // 4096

// ---------------- scratch (device globals; no allocation allowed) ----------
__device__ float g_h1[(size_t)NN * D1];     // 64 MB
__device__ float g_out1[(size_t)NN * D1];   // 64 MB
__device__ float g_h2[NN * HID];            // 8 MB
__device__ float g_out2[NN * HID];          // 8 MB
__device__ float g_wa1[F_IN * 16];          // W1 @ [a_src;a_dst] projections
__device__ float g_as1[NN * HEADS], g_ad1[NN * HEADS];
__device__ float g_as2[NN], g_ad2[NN];
__device__ int   g_deg[NN], g_cur[NN], g_off[NN + 1];
__device__ int   g_esrc[ET];
__device__ int   g_is64;
__device__ float g_g1[512 * 512], g_g2[512 * 128];

// ---------------- helpers ---------------------------------------------------
__device__ __forceinline__ float warpSum(float v) {
    #pragma unroll
    for (int o = 16; o; o >>= 1) v += __shfl_xor_sync(0xffffffffu, v, o);
    return v;
}
__device__ __forceinline__ float warpMax(float v) {
    #pragma unroll
    for (int o = 16; o; o >>= 1) v = fmaxf(v, __shfl_xor_sync(0xffffffffu, v, o));
    return v;
}
__device__ __forceinline__ uint32_t f2tf32(float f) {
    uint32_t o;
    asm("cvt.rna.tf32.f32 %0, %1;" : "=r"(o) : "f"(f));
    return o;
}
__device__ __forceinline__ float lrelu(float v) {
    return v > 0.f ? v : 0.2f * v;
}
// edge_index may be int64 or int32 depending on JAX x64 config; g_is64 set at runtime.
__device__ __forceinline__ int eload(const int* ei, int pos) {
    return g_is64 ? ei[2 * pos] : ei[pos];
}
__device__ __forceinline__ int esrc_of(const int* ei, int e) {
    return (e < NE) ? eload(ei, e) : (e - NE);
}
__device__ __forceinline__ int edst_of(const int* ei, int e) {
    return (e < NE) ? eload(ei, NE + e) : (e - NE);
}

// ---------------- dtype sniff + CSR build ----------------------------------
__global__ void detect_init_kernel(const int* __restrict__ ei) {
    int i = blockIdx.x * blockDim.x + threadIdx.x;
    if (i == 0) {
        int all0 = 1;
        for (int k = 1; k < 64; k += 2) all0 &= (ei[k] == 0);
        g_is64 = all0;
    }
    if (i < NN) { g_deg[i] = 0; g_cur[i] = 0; }
}

__global__ void count_kernel(const int* __restrict__ ei) {
    int e = blockIdx.x * blockDim.x + threadIdx.x;
    if (e >= ET) return;
    atomicAdd(&g_deg[edst_of(ei, e)], 1);
}

__global__ void scan_kernel() {
    __shared__ int ws[32];
    int t = threadIdx.x, lane = t & 31, wid = t >> 5;
    int a0 = g_deg[4 * t + 0], a1 = g_deg[4 * t + 1];
    int a2 = g_deg[4 * t + 2], a3 = g_deg[4 * t + 3];
    int tsum = a0 + a1 + a2 + a3;
    int x = tsum;
    #pragma unroll
    for (int o = 1; o < 32; o <<= 1) {
        int y = __shfl_up_sync(0xffffffffu, x, o);
        if (lane >= o) x += y;
    }
    if (lane == 31) ws[wid] = x;
    __syncthreads();
    if (wid == 0) {
        int y = ws[lane];
        #pragma unroll
        for (int o = 1; o < 32; o <<= 1) {
            int z = __shfl_up_sync(0xffffffffu, y, o);
            if (lane >= o) y += z;
        }
        ws[lane] = y;
    }
    __syncthreads();
    int base = (wid ? ws[wid - 1] : 0) + (x - tsum);
    g_off[4 * t + 0] = base;
    g_off[4 * t + 1] = base + a0;
    g_off[4 * t + 2] = base + a0 + a1;
    g_off[4 * t + 3] = base + a0 + a1 + a2;
    if (t == 1023) g_off[NN] = base + tsum;
}

__global__ void fill_kernel(const int* __restrict__ ei) {
    int e = blockIdx.x * blockDim.x + threadIdx.x;
    if (e >= ET) return;
    int s = esrc_of(ei, e), d = edst_of(ei, e);
    int p = g_off[d] + atomicAdd(&g_cur[d], 1);
    g_esrc[p] = s;
}

// ---------------- TF32 tensor-core GEMM (mma.sync, double-buffered) ----------
// A[M,K] rm, B[K,N] rm, C[M,N]. Requires M%BM==0, N%BN==0, K%32==0.
template<int BM, int BN, int WM, int WN>
__global__ __launch_bounds__((BM / WM) * (BN / WN) * 32)
void tf32gemm(const float* __restrict__ A, const float* __restrict__ B,
              const float* __restrict__ bias, float* __restrict__ C,
              int M, int N, int K, int relu)
{
    constexpr int BK = 32;
    constexpr int WARPS = (BM / WM) * (BN / WN);
    constexpr int THREADS = WARPS * 32;
    constexpr int MF = WM / 16, NF = WN / 8;
    constexpr int AST = BK + 4;   // A-frag LDS conflict-free
    constexpr int BST = BN + 4;   // B-frag max 2-way
    constexpr int ALD = (BM * BK) / (4 * THREADS);
    constexpr int BLD = (BK * BN) / (4 * THREADS);
    constexpr int STAGE = BM * AST + BK * BST;

    extern __shared__ uint32_t smem_dyn[];
    const int tid = threadIdx.x;
    const int wid = tid >> 5, lane = tid & 31;
    const int wm = wid / (BN / WN), wn = wid % (BN / WN);
    const int g = lane >> 2, tg = lane & 3;
    const int row0 = blockIdx.y * BM, col0 = blockIdx.x * BN;

    float acc[MF][NF][4];
    #pragma unroll
    for (int i = 0; i < MF; i++)
        #pragma unroll
        for (int j = 0; j < NF; j++)
            #pragma unroll
            for (int q = 0; q < 4; q++) acc[i][j][q] = 0.f;

    float4 pa[ALD], pb[BLD];
    auto ldAB = [&](int k0) {
        #pragma unroll
        for (int j = 0; j < ALD; j++) {
            int fid = tid + j * THREADS;
            int r = fid / (BK / 4), c4 = fid % (BK / 4);
            pa[j] = *reinterpret_cast<const float4*>(A + (size_t)(row0 + r) * K + k0 + c4 * 4);
        }
        #pragma unroll
        for (int j = 0; j < BLD; j++) {
            int fid = tid + j * THREADS;
            int r = fid / (BN / 4), c4 = fid % (BN / 4);
            pb[j] = *reinterpret_cast<const float4*>(B + (size_t)(k0 + r) * N + col0 + c4 * 4);
        }
    };
    auto stash = [&](int buf) {
        uint32_t* As = smem_dyn + buf * STAGE;
        uint32_t* Bs = As + BM * AST;
        #pragma unroll
        for (int j = 0; j < ALD; j++) {
            int fid = tid + j * THREADS;
            int r = fid / (BK / 4), c4 = fid % (BK / 4);
            uint4 v;
            v.x = f2tf32(pa[j].x); v.y = f2tf32(pa[j].y);
            v.z = f2tf32(pa[j].z); v.w = f2tf32(pa[j].w);
            *reinterpret_cast<uint4*>(&As[r * AST + c4 * 4]) = v;
        }
        #pragma unroll
        for (int j = 0; j < BLD; j++) {
            int fid = tid + j * THREADS;
            int r = fid / (BN / 4), c4 = fid % (BN / 4);
            uint4 v;
            v.x = f2tf32(pb[j].x); v.y = f2tf32(pb[j].y);
            v.z = f2tf32(pb[j].z); v.w = f2tf32(pb[j].w);
            *reinterpret_cast<uint4*>(&Bs[r * BST + c4 * 4]) = v;
        }
    };

    ldAB(0);
    stash(0);
    __syncthreads();

    const int niter = K / BK;
    for (int it = 0; it < niter; ++it) {
        const int cur = it & 1;
        if (it + 1 < niter) ldAB((it + 1) * BK);
        const uint32_t* As = smem_dyn + cur * STAGE;
        const uint32_t* Bs = As + BM * AST;
        #pragma unroll
        for (int kk = 0; kk < 4; kk++) {
            uint32_t af[MF][4], bf[NF][2];
            #pragma unroll
            for (int mf = 0; mf < MF; mf++) {
                int r = wm * WM + mf * 16;
                af[mf][0] = As[(r + g    ) * AST + kk * 8 + tg    ];
                af[mf][1] = As[(r + g + 8) * AST + kk * 8 + tg    ];
                af[mf][2] = As[(r + g    ) * AST + kk * 8 + tg + 4];
                af[mf][3] = As[(r + g + 8) * AST + kk * 8 + tg + 4];
            }
            #pragma unroll
            for (int nf = 0; nf < NF; nf++) {
                int c = wn * WN + nf * 8 + g;
                bf[nf][0] = Bs[(kk * 8 + tg    ) * BST + c];
                bf[nf][1] = Bs[(kk * 8 + tg + 4) * BST + c];
            }
            #pragma unroll
            for (int mf = 0; mf < MF; mf++)
                #pragma unroll
                for (int nf = 0; nf < NF; nf++)
                    asm volatile(
                        "mma.sync.aligned.m16n8k8.row.col.f32.tf32.tf32.f32 "
                        "{%0,%1,%2,%3},{%4,%5,%6,%7},{%8,%9},{%0,%1,%2,%3};\n"
                        : "+f"(acc[mf][nf][0]), "+f"(acc[mf][nf][1]),
                          "+f"(acc[mf][nf][2]), "+f"(acc[mf][nf][3])
                        : "r"(af[mf][0]), "r"(af[mf][1]),
                          "r"(af[mf][2]), "r"(af[mf][3]),
                          "r"(bf[nf][0]), "r"(bf[nf][1]));
        }
        if (it + 1 < niter) {
            stash(1 - cur);
            __syncthreads();
        }
    }
    #pragma unroll
    for (int mf = 0; mf < MF; mf++) {
        int r = row0 + wm * WM + mf * 16 + g;
        #pragma unroll
        for (int nf = 0; nf < NF; nf++) {
            int c = col0 + wn * WN + nf * 8 + tg * 2;
            float b0v = bias ? bias[c] : 0.f;
            float b1v = bias ? bias[c + 1] : 0.f;
            float v0 = acc[mf][nf][0] + b0v, v1 = acc[mf][nf][1] + b1v;
            float v2 = acc[mf][nf][2] + b0v, v3 = acc[mf][nf][3] + b1v;
            if (relu) {
                v0 = fmaxf(v0, 0.f); v1 = fmaxf(v1, 0.f);
                v2 = fmaxf(v2, 0.f); v3 = fmaxf(v3, 0.f);
            }
            *reinterpret_cast<float2*>(C + (size_t)r * N + c) = make_float2(v0, v1);
            *reinterpret_cast<float2*>(C + (size_t)(r + 8) * N + c) = make_float2(v2, v3);
        }
    }
}

// ---------------- fp32 tiled SGEMM (tail GEMM only) --------------------------
template<int BM, int BN, int BK, int TM, int TN>
__global__ __launch_bounds__((BM / TM) * (BN / TN))
void sgemm(const float* __restrict__ A, const float* __restrict__ B,
           const float* __restrict__ bias, float* __restrict__ C,
           int M, int N, int K, int relu)
{
    constexpr int THREADS = (BM / TM) * (BN / TN);
    __shared__ float As[BK][BM];
    __shared__ float Bs[BK][BN];
    const int tid = threadIdx.x;
    const int row0 = blockIdx.y * BM, col0 = blockIdx.x * BN;
    const int tr = (tid / (BN / TN)) * TM;
    const int tc = (tid % (BN / TN)) * TN;
    const bool vb = (N % 4) == 0;

    float acc[TM][TN];
    #pragma unroll
    for (int i = 0; i < TM; i++)
        #pragma unroll
        for (int j = 0; j < TN; j++) acc[i][j] = 0.f;

    for (int k0 = 0; k0 < K; k0 += BK) {
        #pragma unroll 4
        for (int i = tid * 4; i < BM * BK; i += THREADS * 4) {
            int r = i / BK, c = i % BK;
            int gr = row0 + r, gc = k0 + c;
            float4 v = make_float4(0.f, 0.f, 0.f, 0.f);
            if (gr < M) v = *reinterpret_cast<const float4*>(A + (size_t)gr * K + gc);
            As[c + 0][r] = v.x; As[c + 1][r] = v.y;
            As[c + 2][r] = v.z; As[c + 3][r] = v.w;
        }
        #pragma unroll 4
        for (int i = tid * 4; i < BK * BN; i += THREADS * 4) {
            int r = i / BN, c = i % BN;
            int gr = k0 + r, gc = col0 + c;
            float vv0 = 0.f, vv1 = 0.f, vv2 = 0.f, vv3 = 0.f;
            if (vb && gc + 3 < N) {
                float4 v = *reinterpret_cast<const float4*>(B + (size_t)gr * N + gc);
                vv0 = v.x; vv1 = v.y; vv2 = v.z; vv3 = v.w;
            } else {
                if (gc + 0 < N) vv0 = B[(size_t)gr * N + gc + 0];
                if (gc + 1 < N) vv1 = B[(size_t)gr * N + gc + 1];
                if (gc + 2 < N) vv2 = B[(size_t)gr * N + gc + 2];
                if (gc + 3 < N) vv3 = B[(size_t)gr * N + gc + 3];
            }
            Bs[r][c + 0] = vv0; Bs[r][c + 1] = vv1;
            Bs[r][c + 2] = vv2; Bs[r][c + 3] = vv3;
        }
        __syncthreads();
        #pragma unroll
        for (int kk = 0; kk < BK; kk++) {
            float ar[TM], br[TN];
            #pragma unroll
            for (int i = 0; i < TM; i++) ar[i] = As[kk][tr + i];
            #pragma unroll
            for (int j = 0; j < TN; j++) br[j] = Bs[kk][tc + j];
            #pragma unroll
            for (int i = 0; i < TM; i++)
                #pragma unroll
                for (int j = 0; j < TN; j++) acc[i][j] += ar[i] * br[j];
        }
        __syncthreads();
    }
    #pragma unroll
    for (int i = 0; i < TM; i++) {
        int r = row0 + tr + i;
        if (r >= M) continue;
        #pragma unroll
        for (int j = 0; j < TN; j++) {
            int c = col0 + tc + j;
            if (c >= N) continue;
            float v = acc[i][j] + (bias ? bias[c] : 0.f);
            if (relu) v = fmaxf(v, 0.f);
            C[(size_t)r * N + c] = v;
        }
    }
}

// ---------------- GAT layer 1 -------------------------------------------------
// wa[f][o] = sum_c W1[f][h*512+c] * a[h][c], o in [0,16): 0-7 src, 8-15 dst
__global__ void prep_wa1_kernel(const float* __restrict__ W1,
                                const float* __restrict__ a1s,
                                const float* __restrict__ a1d) {
    int f = blockIdx.x;
    int w = threadIdx.x >> 5, lane = threadIdx.x & 31;   // 16 warps
    int h = w & 7;
    const float* a = (w < 8) ? a1s : a1d;
    float s = 0.f;
    for (int c = lane; c < HID; c += 32)
        s += W1[(size_t)f * D1 + h * HID + c] * a[h * HID + c];
    s = warpSum(s);
    if (lane == 0) g_wa1[f * 16 + w] = s;
}

// alpha_src/dst[n][h] = x[n,:] @ wa1[:, h]   (exact linear-algebra fusion)
__global__ void alpha1_fast_kernel(const float* __restrict__ x) {
    int n = blockIdx.x * 8 + (threadIdx.x >> 5);
    int lane = threadIdx.x & 31;
    float xv[4];
    #pragma unroll
    for (int j = 0; j < 4; j++) xv[j] = x[(size_t)n * F_IN + lane + 32 * j];
    #pragma unroll
    for (int o = 0; o < 16; o++) {
        float s = 0.f;
        #pragma unroll
        for (int j = 0; j < 4; j++) s += xv[j] * g_wa1[(lane + 32 * j) * 16 + o];
        s = warpSum(s);
        if (lane == 0) {
            if (o < 8) g_as1[n * 8 + o] = s;
            else       g_ad1[n * 8 + (o - 8)] = s;
        }
    }
}

// fused leaky-relu logits + segment-softmax + weighted gather-aggregate (L1)
#define CH1 128
__global__ __launch_bounds__(256)
void norm_agg1_kernel(const float* __restrict__ b1) {
    __shared__ float sm[HEADS], sinv[HEADS], sadn[HEADS];
    __shared__ float sal[CH1 * HEADS];
    __shared__ int   ssrc[CH1];
    int n = blockIdx.x;
    int t = threadIdx.x, w = t >> 5, lane = t & 31;   // warp w = head w
    int beg = g_off[n], end = g_off[n + 1];

    float adn = g_ad1[n * HEADS + w];
    if (lane == 0) sadn[w] = adn;
    float m = -3.4e38f;
    for (int i = beg + lane; i < end; i += 32)
        m = fmaxf(m, lrelu(g_as1[g_esrc[i] * HEADS + w] + adn));
    m = warpMax(m);
    float s = 0.f;
    for (int i = beg + lane; i < end; i += 32)
        s += expf(lrelu(g_as1[g_esrc[i] * HEADS + w] + adn) - m);
    s = warpSum(s);
    if (lane == 0) { sm[w] = m; sinv[w] = 1.f / s; }
    __syncthreads();

    int c0 = t * 16;
    int head = c0 >> 9;
    float acc[16];
    #pragma unroll
    for (int j = 0; j < 16; j++) acc[j] = 0.f;

    for (int cs = beg; cs < end; cs += CH1) {
        int cnt = min(end - cs, CH1);
        for (int j = t; j < cnt; j += 256) ssrc[j] = g_esrc[cs + j];
        __syncthreads();
        for (int j = t; j < cnt * HEADS; j += 256) {
            int i = j >> 3, h = j & 7;
            float v = lrelu(g_as1[ssrc[i] * HEADS + h] + sadn[h]);
            sal[j] = expf(v - sm[h]) * sinv[h];
        }
        __syncthreads();
        #pragma unroll 2
        for (int i = 0; i < cnt; i++) {
            float al = sal[i * HEADS + head];
            const float4* hs = reinterpret_cast<const float4*>(
                g_h1 + (size_t)ssrc[i] * D1 + c0);
            #pragma unroll
            for (int j = 0; j < 4; j++) {
                float4 v = hs[j];
                acc[4 * j + 0] += v.x * al; acc[4 * j + 1] += v.y * al;
                acc[4 * j + 2] += v.z * al; acc[4 * j + 3] += v.w * al;
            }
        }
        __syncthreads();
    }
    float* o = g_out1 + (size_t)n * D1 + c0;
    #pragma unroll
    for (int j = 0; j < 16; j++)
        o[j] = fmaxf(acc[j] + b1[c0 + j], 0.f);        // relu after GAT1
}

// ---------------- GAT layer 2 -------------------------------------------------
__global__ void alpha2_kernel(const float* __restrict__ asrc,
                              const float* __restrict__ adst) {
    int n = blockIdx.x * 8 + (threadIdx.x >> 5);
    int lane = threadIdx.x & 31;
    const float* hrow = g_h2 + (size_t)n * HID;
    float s1 = 0.f, s2 = 0.f;
    for (int c = lane; c < HID; c += 32) {
        float v = hrow[c];
        s1 += v * asrc[c];
        s2 += v * adst[c];
    }
    s1 = warpSum(s1); s2 = warpSum(s2);
    if (lane == 0) { g_as2[n] = s1; g_ad2[n] = s2; }
}

// fused leaky-relu logits + segment-softmax + aggregate (L2)
#define CH2 256
__global__ __launch_bounds__(128)
void norm_agg2_kernel(const float* __restrict__ b2) {
    __shared__ float sred[4];
    __shared__ float sal[CH2];
    __shared__ int   ssrc[CH2];
    int n = blockIdx.x;
    int t = threadIdx.x, w = t >> 5, lane = t & 31;
    int beg = g_off[n], end = g_off[n + 1];
    float adn = g_ad2[n];

    float m = -3.4e38f;
    for (int i = beg + t; i < end; i += 128)
        m = fmaxf(m, lrelu(g_as2[g_esrc[i]] + adn));
    m = warpMax(m);
    if (lane == 0) sred[w] = m;
    __syncthreads();
    m = fmaxf(fmaxf(sred[0], sred[1]), fmaxf(sred[2], sred[3]));
    __syncthreads();
    float s = 0.f;
    for (int i = beg + t; i < end; i += 128)
        s += expf(lrelu(g_as2[g_esrc[i]] + adn) - m);
    s = warpSum(s);
    if (lane == 0) sred[w] = s;
    __syncthreads();
    float inv = 1.f / (sred[0] + sred[1] + sred[2] + sred[3]);

    int c0 = t * 4;
    float a0 = 0.f, a1 = 0.f, a2 = 0.f, a3 = 0.f;
    for (int cs = beg; cs < end; cs += CH2) {
        int cnt = min(end - cs, CH2);
        __syncthreads();
        for (int j = t; j < cnt; j += 128) {
            int sc = g_esrc[cs + j];
            ssrc[j] = sc;
            sal[j] = expf(lrelu(g_as2[sc] + adn) - m) * inv;
        }
        __syncthreads();
        #pragma unroll 2
        for (int i = 0; i < cnt; i++) {
            float al = sal[i];
            float4 v = *reinterpret_cast<const float4*>(
                g_h2 + (size_t)ssrc[i] * HID + c0);
            a0 += v.x * al; a1 += v.y * al; a2 += v.z * al; a3 += v.w * al;
        }
    }
    float* o = g_out2 + (size_t)n * HID + c0;
    o[0] = fmaxf(a0 + b2[c0 + 0], 0.f);
    o[1] = fmaxf(a1 + b2[c0 + 1], 0.f);
    o[2] = fmaxf(a2 + b2[c0 + 2], 0.f);
    o[3] = fmaxf(a3 + b2[c0 + 3], 0.f);
}

// ---------------- launch -----------------------------------------------------
static inline int smem_bytes(int BM, int BN) {
    return 2 * (BM * 36 + 32 * (BN + 4)) * 4;
}

extern "C" void kernel_launch(void* const* d_in, const int* in_sizes, int n_in,
                              void* d_out, int out_size) {
    const float* x      = (const float*)d_in[0];
    const int*   ei     = (const int*)d_in[1];
    const float* W1     = (const float*)d_in[3];
    const float* a_src1 = (const float*)d_in[4];
    const float* a_dst1 = (const float*)d_in[5];
    const float* b1     = (const float*)d_in[6];
    const float* W2     = (const float*)d_in[7];
    const float* a_src2 = (const float*)d_in[8];
    const float* a_dst2 = (const float*)d_in[9];
    const float* b2     = (const float*)d_in[10];
    const float* fc1w   = (const float*)d_in[11];
    const float* fc1b   = (const float*)d_in[12];
    const float* fc2w   = (const float*)d_in[13];
    const float* fc2b   = (const float*)d_in[14];
    const float* fc3w   = (const float*)d_in[15];
    const float* fc3b   = (const float*)d_in[16];
    float* out = (float*)d_out;

    float *h1, *o1, *h2, *o2, *gg1, *gg2;
    cudaGetSymbolAddress((void**)&h1,  g_h1);
    cudaGetSymbolAddress((void**)&o1,  g_out1);
    cudaGetSymbolAddress((void**)&h2,  g_h2);
    cudaGetSymbolAddress((void**)&o2,  g_out2);
    cudaGetSymbolAddress((void**)&gg1, g_g1);
    cudaGetSymbolAddress((void**)&gg2, g_g2);

    const int SM_BIG   = smem_bytes(128, 128);   // 70656 B
    const int SM_SMALL = smem_bytes(64, 64);     // 35840 B
    cudaFuncSetAttribute(tf32gemm<128, 128, 64, 32>,
                         cudaFuncAttributeMaxDynamicSharedMemorySize, SM_BIG);
    cudaFuncSetAttribute(tf32gemm<64, 64, 32, 32>,
                         cudaFuncAttributeMaxDynamicSharedMemorySize, SM_SMALL);

    // Launches 1-5: alpha projection + CSR head (input-only deps).
    // Launch 6 is GEMM1 — ncu's `-s 5 -c 1` profiles it next capture.
    prep_wa1_kernel<<<F_IN, 512>>>(W1, a_src1, a_dst1);        // 1
    alpha1_fast_kernel<<<NN / 8, 256>>>(x);                    // 2
    detect_init_kernel<<<(NN + 255) / 256, 256>>>(ei);         // 3
    count_kernel<<<(ET + 255) / 256, 256>>>(ei);               // 4
    scan_kernel<<<1, 1024>>>();                                // 5

    // 6: GAT layer 1 GEMM h1 = x @ W1 (TF32 tensor cores)
    tf32gemm<128, 128, 64, 32><<<dim3(D1 / 128, NN / 128), 256, SM_BIG>>>(
        x, W1, nullptr, h1, NN, D1, F_IN, 0);

    // 7: CSR fill (needed only by norm_agg1)
    fill_kernel<<<(ET + 255) / 256, 256>>>(ei);
    // 8: fused softmax+aggregate
    norm_agg1_kernel<<<NN, 256>>>(b1);

    // GAT layer 2: h2 = out1 @ W2 (TF32 tensor cores)
    tf32gemm<128, 128, 64, 32><<<dim3(HID / 128, NN / 128), 256, SM_BIG>>>(
        o1, W2, nullptr, h2, NN, HID, D1, 0);
    alpha2_kernel<<<NN / 8, 256>>>(a_src2, a_dst2);
    norm_agg2_kernel<<<NN, 128>>>(b2);

    // MLP head: g = out2 viewed as [512, 4096]
    tf32gemm<64, 64, 32, 32><<<dim3(512 / 64, 512 / 64), 128, SM_SMALL>>>(
        o2, fc1w, fc1b, gg1, 512, 512, D1, 1);
    tf32gemm<64, 64, 32, 32><<<dim3(128 / 64, 512 / 64), 128, SM_SMALL>>>(
        gg1, fc2w, fc2b, gg2, 512, 128, 512, 1);
    sgemm<64, 64, 16, 4, 4><<<dim3(1, 512 / 64), 256>>>(
        gg2, fc3w, fc3b, out, 512, 10, 128, 0);
}

// round 14
// speedup vs baseline: 1.6565x; 1.1355x over previous
#include <cuda_runtime.h>
#include <cstdint>

#define NN   4096
#define NE   32768
#define ET   (NE + NN)        // edges + self loops = 36864
#define F_IN 128
#define HEADS 8
#define HID  512
#define D1   (HEADS * HID)    // 4096

// ---------------- scratch (device globals; no allocation allowed) ----------
__device__ float g_h1[(size_t)NN * D1];     // 64 MB
__device__ float g_out1[(size_t)NN * D1];   // 64 MB
__device__ float g_h2[NN * HID];            // 8 MB
__device__ float g_out2[NN * HID];          // 8 MB
__device__ float g_wa1[F_IN * 16];          // W1 @ [a_src;a_dst] projections
__device__ float g_as1[NN * HEADS], g_ad1[NN * HEADS];
__device__ float g_as2[NN], g_ad2[NN];
__device__ int   g_deg[NN], g_cur[NN], g_off[NN + 1];
__device__ int   g_esrc[ET];
__device__ int   g_is64;
__device__ float g_g1[512 * 512], g_g2[512 * 128];

// ---------------- helpers ---------------------------------------------------
__device__ __forceinline__ float warpSum(float v) {
    #pragma unroll
    for (int o = 16; o; o >>= 1) v += __shfl_xor_sync(0xffffffffu, v, o);
    return v;
}
__device__ __forceinline__ float warpMax(float v) {
    #pragma unroll
    for (int o = 16; o; o >>= 1) v = fmaxf(v, __shfl_xor_sync(0xffffffffu, v, o));
    return v;
}
// pack two fp32 into fp16x2: low half = lo, high half = hi
__device__ __forceinline__ uint32_t f2h2(float lo, float hi) {
    uint32_t r;
    asm("cvt.rn.f16x2.f32 %0, %1, %2;" : "=r"(r) : "f"(hi), "f"(lo));
    return r;
}
__device__ __forceinline__ float lrelu(float v) {
    return v > 0.f ? v : 0.2f * v;
}
// edge_index may be int64 or int32 depending on JAX x64 config; g_is64 set at runtime.
__device__ __forceinline__ int eload(const int* ei, int pos) {
    return g_is64 ? ei[2 * pos] : ei[pos];
}
__device__ __forceinline__ int esrc_of(const int* ei, int e) {
    return (e < NE) ? eload(ei, e) : (e - NE);
}
__device__ __forceinline__ int edst_of(const int* ei, int e) {
    return (e < NE) ? eload(ei, NE + e) : (e - NE);
}

// ---------------- dtype sniff + CSR build ----------------------------------
__global__ void detect_init_kernel(const int* __restrict__ ei) {
    int i = blockIdx.x * blockDim.x + threadIdx.x;
    if (i == 0) {
        int all0 = 1;
        for (int k = 1; k < 64; k += 2) all0 &= (ei[k] == 0);
        g_is64 = all0;
    }
    if (i < NN) { g_deg[i] = 0; g_cur[i] = 0; }
}

__global__ void count_kernel(const int* __restrict__ ei) {
    int e = blockIdx.x * blockDim.x + threadIdx.x;
    if (e >= ET) return;
    atomicAdd(&g_deg[edst_of(ei, e)], 1);
}

__global__ void scan_kernel() {
    __shared__ int ws[32];
    int t = threadIdx.x, lane = t & 31, wid = t >> 5;
    int a0 = g_deg[4 * t + 0], a1 = g_deg[4 * t + 1];
    int a2 = g_deg[4 * t + 2], a3 = g_deg[4 * t + 3];
    int tsum = a0 + a1 + a2 + a3;
    int x = tsum;
    #pragma unroll
    for (int o = 1; o < 32; o <<= 1) {
        int y = __shfl_up_sync(0xffffffffu, x, o);
        if (lane >= o) x += y;
    }
    if (lane == 31) ws[wid] = x;
    __syncthreads();
    if (wid == 0) {
        int y = ws[lane];
        #pragma unroll
        for (int o = 1; o < 32; o <<= 1) {
            int z = __shfl_up_sync(0xffffffffu, y, o);
            if (lane >= o) y += z;
        }
        ws[lane] = y;
    }
    __syncthreads();
    int base = (wid ? ws[wid - 1] : 0) + (x - tsum);
    g_off[4 * t + 0] = base;
    g_off[4 * t + 1] = base + a0;
    g_off[4 * t + 2] = base + a0 + a1;
    g_off[4 * t + 3] = base + a0 + a1 + a2;
    if (t == 1023) g_off[NN] = base + tsum;
}

__global__ void fill_kernel(const int* __restrict__ ei) {
    int e = blockIdx.x * blockDim.x + threadIdx.x;
    if (e >= ET) return;
    int s = esrc_of(ei, e), d = edst_of(ei, e);
    int p = g_off[d] + atomicAdd(&g_cur[d], 1);
    g_esrc[p] = s;
}

// ---------------- FP16 tensor-core GEMM (mma.sync m16n8k16, dbl-buffered) ----
// A[M,K] rm fp32, B[K,N] rm fp32, C[M,N] fp32. M%BM==0, N%BN==0, K%32==0.
// fp32 -> fp16 (rn) on the smem-stash path; fp32 accumulate.
// SMEM: A as [BM][AST=20] uint32 (16 half2 k-pairs + 4 pad)  -> frag LDS conflict-free
//       B as [kpair=16][BN+8] uint32 (half2 of rows 2p,2p+1) -> frag LDS conflict-free
template<int BM, int BN, int WM, int WN>
__global__ __launch_bounds__((BM / WM) * (BN / WN) * 32)
void h16gemm(const float* __restrict__ A, const float* __restrict__ B,
             const float* __restrict__ bias, float* __restrict__ C,
             int M, int N, int K, int relu)
{
    constexpr int BK = 32;
    constexpr int WARPS = (BM / WM) * (BN / WN);
    constexpr int THREADS = WARPS * 32;
    constexpr int MF = WM / 16, NF = WN / 8;
    constexpr int AST  = 20;        // uint32 stride per A row
    constexpr int BSTn = BN + 8;    // uint32 stride per B k-pair row
    constexpr int ALD = (BM * BK) / (4 * THREADS);       // float4/thread (A)
    constexpr int BLD = ((BK / 2) * (BN / 4)) / THREADS; // transpose units/thread
    constexpr int STAGE = BM * AST + (BK / 2) * BSTn;    // uint32

    extern __shared__ uint32_t smem_dyn[];
    const int tid = threadIdx.x;
    const int wid = tid >> 5, lane = tid & 31;
    const int wm = wid / (BN / WN), wn = wid % (BN / WN);
    const int g = lane >> 2, tg = lane & 3;
    const int row0 = blockIdx.y * BM, col0 = blockIdx.x * BN;

    float acc[MF][NF][4];
    #pragma unroll
    for (int i = 0; i < MF; i++)
        #pragma unroll
        for (int j = 0; j < NF; j++)
            #pragma unroll
            for (int q = 0; q < 4; q++) acc[i][j][q] = 0.f;

    float4 pa[ALD];
    float4 pb[BLD][2];
    auto ldAB = [&](int k0) {
        #pragma unroll
        for (int j = 0; j < ALD; j++) {
            int fid = tid + j * THREADS;
            int r = fid >> 3, c4 = fid & 7;           // 8 float4 per 32-float row
            pa[j] = *reinterpret_cast<const float4*>(
                A + (size_t)(row0 + r) * K + k0 + c4 * 4);
        }
        #pragma unroll
        for (int j = 0; j < BLD; j++) {
            int fid = tid + j * THREADS;
            int n = fid % (BN / 4), p = fid / (BN / 4);  // warp: same p, n consecutive
            pb[j][0] = *reinterpret_cast<const float4*>(
                B + (size_t)(k0 + 2 * p    ) * N + col0 + 4 * n);
            pb[j][1] = *reinterpret_cast<const float4*>(
                B + (size_t)(k0 + 2 * p + 1) * N + col0 + 4 * n);
        }
    };
    auto stash = [&](int buf) {
        uint32_t* As = smem_dyn + buf * STAGE;
        uint32_t* Bs = As + BM * AST;
        #pragma unroll
        for (int j = 0; j < ALD; j++) {
            int fid = tid + j * THREADS;
            int r = fid >> 3, c4 = fid & 7;
            uint2 w;
            w.x = f2h2(pa[j].x, pa[j].y);
            w.y = f2h2(pa[j].z, pa[j].w);
            *reinterpret_cast<uint2*>(&As[r * AST + c4 * 2]) = w;
        }
        #pragma unroll
        for (int j = 0; j < BLD; j++) {
            int fid = tid + j * THREADS;
            int n = fid % (BN / 4), p = fid / (BN / 4);
            uint4 w;
            w.x = f2h2(pb[j][0].x, pb[j][1].x);
            w.y = f2h2(pb[j][0].y, pb[j][1].y);
            w.z = f2h2(pb[j][0].z, pb[j][1].z);
            w.w = f2h2(pb[j][0].w, pb[j][1].w);
            *reinterpret_cast<uint4*>(&Bs[p * BSTn + 4 * n]) = w;
        }
    };

    ldAB(0);
    stash(0);
    __syncthreads();

    const int niter = K / BK;
    for (int it = 0; it < niter; ++it) {
        const int cur = it & 1;
        if (it + 1 < niter) ldAB((it + 1) * BK);
        const uint32_t* As = smem_dyn + cur * STAGE;
        const uint32_t* Bs = As + BM * AST;
        #pragma unroll
        for (int kk = 0; kk < 2; kk++) {            // two k16 steps per BK=32
            uint32_t af[MF][4], bf[NF][2];
            #pragma unroll
            for (int mf = 0; mf < MF; mf++) {
                int r = wm * WM + mf * 16;
                af[mf][0] = As[(r + g    ) * AST + kk * 8 + tg    ];
                af[mf][1] = As[(r + g + 8) * AST + kk * 8 + tg    ];
                af[mf][2] = As[(r + g    ) * AST + kk * 8 + tg + 4];
                af[mf][3] = As[(r + g + 8) * AST + kk * 8 + tg + 4];
            }
            #pragma unroll
            for (int nf = 0; nf < NF; nf++) {
                int c = wn * WN + nf * 8 + g;
                bf[nf][0] = Bs[(kk * 8 + tg    ) * BSTn + c];
                bf[nf][1] = Bs[(kk * 8 + tg + 4) * BSTn + c];
            }
            #pragma unroll
            for (int mf = 0; mf < MF; mf++)
                #pragma unroll
                for (int nf = 0; nf < NF; nf++)
                    asm volatile(
                        "mma.sync.aligned.m16n8k16.row.col.f32.f16.f16.f32 "
                        "{%0,%1,%2,%3},{%4,%5,%6,%7},{%8,%9},{%0,%1,%2,%3};\n"
                        : "+f"(acc[mf][nf][0]), "+f"(acc[mf][nf][1]),
                          "+f"(acc[mf][nf][2]), "+f"(acc[mf][nf][3])
                        : "r"(af[mf][0]), "r"(af[mf][1]),
                          "r"(af[mf][2]), "r"(af[mf][3]),
                          "r"(bf[nf][0]), "r"(bf[nf][1]));
        }
        if (it + 1 < niter) {
            stash(1 - cur);
            __syncthreads();
        }
    }
    #pragma unroll
    for (int mf = 0; mf < MF; mf++) {
        int r = row0 + wm * WM + mf * 16 + g;
        #pragma unroll
        for (int nf = 0; nf < NF; nf++) {
            int c = col0 + wn * WN + nf * 8 + tg * 2;
            float b0v = bias ? bias[c] : 0.f;
            float b1v = bias ? bias[c + 1] : 0.f;
            float v0 = acc[mf][nf][0] + b0v, v1 = acc[mf][nf][1] + b1v;
            float v2 = acc[mf][nf][2] + b0v, v3 = acc[mf][nf][3] + b1v;
            if (relu) {
                v0 = fmaxf(v0, 0.f); v1 = fmaxf(v1, 0.f);
                v2 = fmaxf(v2, 0.f); v3 = fmaxf(v3, 0.f);
            }
            *reinterpret_cast<float2*>(C + (size_t)r * N + c) = make_float2(v0, v1);
            *reinterpret_cast<float2*>(C + (size_t)(r + 8) * N + c) = make_float2(v2, v3);
        }
    }
}

// ---------------- fp32 tiled SGEMM (tail GEMM only) --------------------------
template<int BM, int BN, int BK, int TM, int TN>
__global__ __launch_bounds__((BM / TM) * (BN / TN))
void sgemm(const float* __restrict__ A, const float* __restrict__ B,
           const float* __restrict__ bias, float* __restrict__ C,
           int M, int N, int K, int relu)
{
    constexpr int THREADS = (BM / TM) * (BN / TN);
    __shared__ float As[BK][BM];
    __shared__ float Bs[BK][BN];
    const int tid = threadIdx.x;
    const int row0 = blockIdx.y * BM, col0 = blockIdx.x * BN;
    const int tr = (tid / (BN / TN)) * TM;
    const int tc = (tid % (BN / TN)) * TN;
    const bool vb = (N % 4) == 0;

    float acc[TM][TN];
    #pragma unroll
    for (int i = 0; i < TM; i++)
        #pragma unroll
        for (int j = 0; j < TN; j++) acc[i][j] = 0.f;

    for (int k0 = 0; k0 < K; k0 += BK) {
        #pragma unroll 4
        for (int i = tid * 4; i < BM * BK; i += THREADS * 4) {
            int r = i / BK, c = i % BK;
            int gr = row0 + r, gc = k0 + c;
            float4 v = make_float4(0.f, 0.f, 0.f, 0.f);
            if (gr < M) v = *reinterpret_cast<const float4*>(A + (size_t)gr * K + gc);
            As[c + 0][r] = v.x; As[c + 1][r] = v.y;
            As[c + 2][r] = v.z; As[c + 3][r] = v.w;
        }
        #pragma unroll 4
        for (int i = tid * 4; i < BK * BN; i += THREADS * 4) {
            int r = i / BN, c = i % BN;
            int gr = k0 + r, gc = col0 + c;
            float vv0 = 0.f, vv1 = 0.f, vv2 = 0.f, vv3 = 0.f;
            if (vb && gc + 3 < N) {
                float4 v = *reinterpret_cast<const float4*>(B + (size_t)gr * N + gc);
                vv0 = v.x; vv1 = v.y; vv2 = v.z; vv3 = v.w;
            } else {
                if (gc + 0 < N) vv0 = B[(size_t)gr * N + gc + 0];
                if (gc + 1 < N) vv1 = B[(size_t)gr * N + gc + 1];
                if (gc + 2 < N) vv2 = B[(size_t)gr * N + gc + 2];
                if (gc + 3 < N) vv3 = B[(size_t)gr * N + gc + 3];
            }
            Bs[r][c + 0] = vv0; Bs[r][c + 1] = vv1;
            Bs[r][c + 2] = vv2; Bs[r][c + 3] = vv3;
        }
        __syncthreads();
        #pragma unroll
        for (int kk = 0; kk < BK; kk++) {
            float ar[TM], br[TN];
            #pragma unroll
            for (int i = 0; i < TM; i++) ar[i] = As[kk][tr + i];
            #pragma unroll
            for (int j = 0; j < TN; j++) br[j] = Bs[kk][tc + j];
            #pragma unroll
            for (int i = 0; i < TM; i++)
                #pragma unroll
                for (int j = 0; j < TN; j++) acc[i][j] += ar[i] * br[j];
        }
        __syncthreads();
    }
    #pragma unroll
    for (int i = 0; i < TM; i++) {
        int r = row0 + tr + i;
        if (r >= M) continue;
        #pragma unroll
        for (int j = 0; j < TN; j++) {
            int c = col0 + tc + j;
            if (c >= N) continue;
            float v = acc[i][j] + (bias ? bias[c] : 0.f);
            if (relu) v = fmaxf(v, 0.f);
            C[(size_t)r * N + c] = v;
        }
    }
}

// ---------------- GAT layer 1 -------------------------------------------------
// wa[f][o] = sum_c W1[f][h*512+c] * a[h][c], o in [0,16): 0-7 src, 8-15 dst
__global__ void prep_wa1_kernel(const float* __restrict__ W1,
                                const float* __restrict__ a1s,
                                const float* __restrict__ a1d) {
    int f = blockIdx.x;
    int w = threadIdx.x >> 5, lane = threadIdx.x & 31;   // 16 warps
    int h = w & 7;
    const float* a = (w < 8) ? a1s : a1d;
    float s = 0.f;
    for (int c = lane; c < HID; c += 32)
        s += W1[(size_t)f * D1 + h * HID + c] * a[h * HID + c];
    s = warpSum(s);
    if (lane == 0) g_wa1[f * 16 + w] = s;
}

// alpha_src/dst[n][h] = x[n,:] @ wa1[:, h]   (exact linear-algebra fusion)
__global__ void alpha1_fast_kernel(const float* __restrict__ x) {
    int n = blockIdx.x * 8 + (threadIdx.x >> 5);
    int lane = threadIdx.x & 31;
    float xv[4];
    #pragma unroll
    for (int j = 0; j < 4; j++) xv[j] = x[(size_t)n * F_IN + lane + 32 * j];
    #pragma unroll
    for (int o = 0; o < 16; o++) {
        float s = 0.f;
        #pragma unroll
        for (int j = 0; j < 4; j++) s += xv[j] * g_wa1[(lane + 32 * j) * 16 + o];
        s = warpSum(s);
        if (lane == 0) {
            if (o < 8) g_as1[n * 8 + o] = s;
            else       g_ad1[n * 8 + (o - 8)] = s;
        }
    }
}

// fused leaky-relu logits + segment-softmax + weighted gather-aggregate (L1)
#define CH1 128
__global__ __launch_bounds__(256)
void norm_agg1_kernel(const float* __restrict__ b1) {
    __shared__ float sm[HEADS], sinv[HEADS], sadn[HEADS];
    __shared__ float sal[CH1 * HEADS];
    __shared__ int   ssrc[CH1];
    int n = blockIdx.x;
    int t = threadIdx.x, w = t >> 5, lane = t & 31;   // warp w = head w
    int beg = g_off[n], end = g_off[n + 1];

    float adn = g_ad1[n * HEADS + w];
    if (lane == 0) sadn[w] = adn;
    float m = -3.4e38f;
    for (int i = beg + lane; i < end; i += 32)
        m = fmaxf(m, lrelu(g_as1[g_esrc[i] * HEADS + w] + adn));
    m = warpMax(m);
    float s = 0.f;
    for (int i = beg + lane; i < end; i += 32)
        s += expf(lrelu(g_as1[g_esrc[i] * HEADS + w] + adn) - m);
    s = warpSum(s);
    if (lane == 0) { sm[w] = m; sinv[w] = 1.f / s; }
    __syncthreads();

    int c0 = t * 16;
    int head = c0 >> 9;
    float acc[16];
    #pragma unroll
    for (int j = 0; j < 16; j++) acc[j] = 0.f;

    for (int cs = beg; cs < end; cs += CH1) {
        int cnt = min(end - cs, CH1);
        for (int j = t; j < cnt; j += 256) ssrc[j] = g_esrc[cs + j];
        __syncthreads();
        for (int j = t; j < cnt * HEADS; j += 256) {
            int i = j >> 3, h = j & 7;
            float v = lrelu(g_as1[ssrc[i] * HEADS + h] + sadn[h]);
            sal[j] = expf(v - sm[h]) * sinv[h];
        }
        __syncthreads();
        #pragma unroll 2
        for (int i = 0; i < cnt; i++) {
            float al = sal[i * HEADS + head];
            const float4* hs = reinterpret_cast<const float4*>(
                g_h1 + (size_t)ssrc[i] * D1 + c0);
            #pragma unroll
            for (int j = 0; j < 4; j++) {
                float4 v = hs[j];
                acc[4 * j + 0] += v.x * al; acc[4 * j + 1] += v.y * al;
                acc[4 * j + 2] += v.z * al; acc[4 * j + 3] += v.w * al;
            }
        }
        __syncthreads();
    }
    float* o = g_out1 + (size_t)n * D1 + c0;
    #pragma unroll
    for (int j = 0; j < 16; j++)
        o[j] = fmaxf(acc[j] + b1[c0 + j], 0.f);        // relu after GAT1
}

// ---------------- GAT layer 2 -------------------------------------------------
__global__ void alpha2_kernel(const float* __restrict__ asrc,
                              const float* __restrict__ adst) {
    int n = blockIdx.x * 8 + (threadIdx.x >> 5);
    int lane = threadIdx.x & 31;
    const float* hrow = g_h2 + (size_t)n * HID;
    float s1 = 0.f, s2 = 0.f;
    for (int c = lane; c < HID; c += 32) {
        float v = hrow[c];
        s1 += v * asrc[c];
        s2 += v * adst[c];
    }
    s1 = warpSum(s1); s2 = warpSum(s2);
    if (lane == 0) { g_as2[n] = s1; g_ad2[n] = s2; }
}

// fused leaky-relu logits + segment-softmax + aggregate (L2)
#define CH2 256
__global__ __launch_bounds__(128)
void norm_agg2_kernel(const float* __restrict__ b2) {
    __shared__ float sred[4];
    __shared__ float sal[CH2];
    __shared__ int   ssrc[CH2];
    int n = blockIdx.x;
    int t = threadIdx.x, w = t >> 5, lane = t & 31;
    int beg = g_off[n], end = g_off[n + 1];
    float adn = g_ad2[n];

    float m = -3.4e38f;
    for (int i = beg + t; i < end; i += 128)
        m = fmaxf(m, lrelu(g_as2[g_esrc[i]] + adn));
    m = warpMax(m);
    if (lane == 0) sred[w] = m;
    __syncthreads();
    m = fmaxf(fmaxf(sred[0], sred[1]), fmaxf(sred[2], sred[3]));
    __syncthreads();
    float s = 0.f;
    for (int i = beg + t; i < end; i += 128)
        s += expf(lrelu(g_as2[g_esrc[i]] + adn) - m);
    s = warpSum(s);
    if (lane == 0) sred[w] = s;
    __syncthreads();
    float inv = 1.f / (sred[0] + sred[1] + sred[2] + sred[3]);

    int c0 = t * 4;
    float a0 = 0.f, a1 = 0.f, a2 = 0.f, a3 = 0.f;
    for (int cs = beg; cs < end; cs += CH2) {
        int cnt = min(end - cs, CH2);
        __syncthreads();
        for (int j = t; j < cnt; j += 128) {
            int sc = g_esrc[cs + j];
            ssrc[j] = sc;
            sal[j] = expf(lrelu(g_as2[sc] + adn) - m) * inv;
        }
        __syncthreads();
        #pragma unroll 2
        for (int i = 0; i < cnt; i++) {
            float al = sal[i];
            float4 v = *reinterpret_cast<const float4*>(
                g_h2 + (size_t)ssrc[i] * HID + c0);
            a0 += v.x * al; a1 += v.y * al; a2 += v.z * al; a3 += v.w * al;
        }
    }
    float* o = g_out2 + (size_t)n * HID + c0;
    o[0] = fmaxf(a0 + b2[c0 + 0], 0.f);
    o[1] = fmaxf(a1 + b2[c0 + 1], 0.f);
    o[2] = fmaxf(a2 + b2[c0 + 2], 0.f);
    o[3] = fmaxf(a3 + b2[c0 + 3], 0.f);
}

// ---------------- launch -----------------------------------------------------
// STAGE(BM, BN) = BM*20 + 16*(BN+8) uint32, double-buffered, in bytes
static inline int h16_smem_bytes(int BM, int BN) {
    return 2 * (BM * 20 + 16 * (BN + 8)) * 4;
}

extern "C" void kernel_launch(void* const* d_in, const int* in_sizes, int n_in,
                              void* d_out, int out_size) {
    const float* x      = (const float*)d_in[0];
    const int*   ei     = (const int*)d_in[1];
    const float* W1     = (const float*)d_in[3];
    const float* a_src1 = (const float*)d_in[4];
    const float* a_dst1 = (const float*)d_in[5];
    const float* b1     = (const float*)d_in[6];
    const float* W2     = (const float*)d_in[7];
    const float* a_src2 = (const float*)d_in[8];
    const float* a_dst2 = (const float*)d_in[9];
    const float* b2     = (const float*)d_in[10];
    const float* fc1w   = (const float*)d_in[11];
    const float* fc1b   = (const float*)d_in[12];
    const float* fc2w   = (const float*)d_in[13];
    const float* fc2b   = (const float*)d_in[14];
    const float* fc3w   = (const float*)d_in[15];
    const float* fc3b   = (const float*)d_in[16];
    float* out = (float*)d_out;

    float *h1, *o1, *h2, *o2, *gg1, *gg2;
    cudaGetSymbolAddress((void**)&h1,  g_h1);
    cudaGetSymbolAddress((void**)&o1,  g_out1);
    cudaGetSymbolAddress((void**)&h2,  g_h2);
    cudaGetSymbolAddress((void**)&o2,  g_out2);
    cudaGetSymbolAddress((void**)&gg1, g_g1);
    cudaGetSymbolAddress((void**)&gg2, g_g2);

    const int SM_BIG   = h16_smem_bytes(128, 128);   // 37888 B
    const int SM_SMALL = h16_smem_bytes(64, 64);     // 19456 B
    cudaFuncSetAttribute(h16gemm<128, 128, 64, 32>,
                         cudaFuncAttributeMaxDynamicSharedMemorySize, SM_BIG);
    cudaFuncSetAttribute(h16gemm<64, 64, 32, 32>,
                         cudaFuncAttributeMaxDynamicSharedMemorySize, SM_SMALL);

    // alpha projection + CSR head (input-only deps)
    prep_wa1_kernel<<<F_IN, 512>>>(W1, a_src1, a_dst1);
    alpha1_fast_kernel<<<NN / 8, 256>>>(x);
    detect_init_kernel<<<(NN + 255) / 256, 256>>>(ei);
    count_kernel<<<(ET + 255) / 256, 256>>>(ei);
    scan_kernel<<<1, 1024>>>();

    // GAT layer 1 GEMM h1 = x @ W1 (FP16 tensor cores, fp32 accum)
    h16gemm<128, 128, 64, 32><<<dim3(D1 / 128, NN / 128), 256, SM_BIG>>>(
        x, W1, nullptr, h1, NN, D1, F_IN, 0);

    // CSR fill (needed only by norm_agg1)
    fill_kernel<<<(ET + 255) / 256, 256>>>(ei);
    norm_agg1_kernel<<<NN, 256>>>(b1);

    // GAT layer 2: h2 = out1 @ W2 (FP16 tensor cores)
    h16gemm<128, 128, 64, 32><<<dim3(HID / 128, NN / 128), 256, SM_BIG>>>(
        o1, W2, nullptr, h2, NN, HID, D1, 0);
    alpha2_kernel<<<NN / 8, 256>>>(a_src2, a_dst2);
    norm_agg2_kernel<<<NN, 128>>>(b2);

    // MLP head: g = out2 viewed as [512, 4096]
    h16gemm<64, 64, 32, 32><<<dim3(512 / 64, 512 / 64), 128, SM_SMALL>>>(
        o2, fc1w, fc1b, gg1, 512, 512, D1, 1);
    h16gemm<64, 64, 32, 32><<<dim3(128 / 64, 512 / 64), 128, SM_SMALL>>>(
        gg1, fc2w, fc2b, gg2, 512, 128, 512, 1);
    sgemm<64, 64, 16, 4, 4><<<dim3(1, 512 / 64), 256>>>(
        gg2, fc3w, fc3b, out, 512, 10, 128, 0);
}

// round 15
// speedup vs baseline: 2.1702x; 1.3101x over previous
#include <cuda_runtime.h>
#include <cuda_fp16.h>
#include <cstdint>
#include <type_traits>

#define NN   4096
#define NE   32768
#define ET   (NE + NN)        // edges + self loops = 36864
#define F_IN 128
#define HEADS 8
#define HID  512
#define D1   (HEADS * HID)    // 4096

// ---------------- scratch (device globals; no allocation allowed) ----------
__device__ __half g_h1[(size_t)NN * D1];     // 32 MB (fp16)
__device__ __half g_out1[(size_t)NN * D1];   // 32 MB (fp16)
__device__ __half g_h2[NN * HID];            // 4 MB
__device__ __half g_out2[NN * HID];          // 4 MB
__device__ __half g_g1[512 * 512];
__device__ float  g_g2[512 * 128];
__device__ float g_wa1[F_IN * 16];           // W1 @ [a_src;a_dst] projections
__device__ float g_as1[NN * HEADS], g_ad1[NN * HEADS];
__device__ float g_as2[NN], g_ad2[NN];
__device__ int   g_deg[NN], g_cur[NN], g_off[NN + 1];
__device__ int   g_esrc[ET];
__device__ int   g_is64;

// ---------------- helpers ---------------------------------------------------
__device__ __forceinline__ float warpSum(float v) {
    #pragma unroll
    for (int o = 16; o; o >>= 1) v += __shfl_xor_sync(0xffffffffu, v, o);
    return v;
}
__device__ __forceinline__ float warpMax(float v) {
    #pragma unroll
    for (int o = 16; o; o >>= 1) v = fmaxf(v, __shfl_xor_sync(0xffffffffu, v, o));
    return v;
}
// pack two fp32 into fp16x2: low half = lo, high half = hi
__device__ __forceinline__ uint32_t f2h2(float lo, float hi) {
    uint32_t r;
    asm("cvt.rn.f16x2.f32 %0, %1, %2;" : "=r"(r) : "f"(hi), "f"(lo));
    return r;
}
// unpack fp16x2 -> float2
__device__ __forceinline__ float2 h2f2(uint32_t u) {
    return __half22float2(*reinterpret_cast<const __half2*>(&u));
}
__device__ __forceinline__ float lrelu(float v) {
    return v > 0.f ? v : 0.2f * v;
}
// edge_index may be int64 or int32 depending on JAX x64 config; g_is64 set at runtime.
__device__ __forceinline__ int eload(const int* ei, int pos) {
    return g_is64 ? ei[2 * pos] : ei[pos];
}
__device__ __forceinline__ int esrc_of(const int* ei, int e) {
    return (e < NE) ? eload(ei, e) : (e - NE);
}
__device__ __forceinline__ int edst_of(const int* ei, int e) {
    return (e < NE) ? eload(ei, NE + e) : (e - NE);
}

// ---------------- dtype sniff + CSR build ----------------------------------
__global__ void detect_init_kernel(const int* __restrict__ ei) {
    int i = blockIdx.x * blockDim.x + threadIdx.x;
    if (i == 0) {
        int all0 = 1;
        for (int k = 1; k < 64; k += 2) all0 &= (ei[k] == 0);
        g_is64 = all0;
    }
    if (i < NN) { g_deg[i] = 0; g_cur[i] = 0; }
}

__global__ void count_kernel(const int* __restrict__ ei) {
    int e = blockIdx.x * blockDim.x + threadIdx.x;
    if (e >= ET) return;
    atomicAdd(&g_deg[edst_of(ei, e)], 1);
}

__global__ void scan_kernel() {
    __shared__ int ws[32];
    int t = threadIdx.x, lane = t & 31, wid = t >> 5;
    int a0 = g_deg[4 * t + 0], a1 = g_deg[4 * t + 1];
    int a2 = g_deg[4 * t + 2], a3 = g_deg[4 * t + 3];
    int tsum = a0 + a1 + a2 + a3;
    int x = tsum;
    #pragma unroll
    for (int o = 1; o < 32; o <<= 1) {
        int y = __shfl_up_sync(0xffffffffu, x, o);
        if (lane >= o) x += y;
    }
    if (lane == 31) ws[wid] = x;
    __syncthreads();
    if (wid == 0) {
        int y = ws[lane];
        #pragma unroll
        for (int o = 1; o < 32; o <<= 1) {
            int z = __shfl_up_sync(0xffffffffu, y, o);
            if (lane >= o) y += z;
        }
        ws[lane] = y;
    }
    __syncthreads();
    int base = (wid ? ws[wid - 1] : 0) + (x - tsum);
    g_off[4 * t + 0] = base;
    g_off[4 * t + 1] = base + a0;
    g_off[4 * t + 2] = base + a0 + a1;
    g_off[4 * t + 3] = base + a0 + a1 + a2;
    if (t == 1023) g_off[NN] = base + tsum;
}

__global__ void fill_kernel(const int* __restrict__ ei) {
    int e = blockIdx.x * blockDim.x + threadIdx.x;
    if (e >= ET) return;
    int s = esrc_of(ei, e), d = edst_of(ei, e);
    int p = g_off[d] + atomicAdd(&g_cur[d], 1);
    g_esrc[p] = s;
}

// ---------------- FP16 tensor-core GEMM (mma.sync m16n8k16, dbl-buffered) ----
// A[M,K] rm (fp32 or fp16), B[K,N] rm fp32, C[M,N] (fp32 or fp16).
// M%BM==0, N%BN==0, K%32==0. fp32 accumulate.
// SMEM: A as [BM][AST=20] uint32 (16 half2 k-pairs + 4 pad)  -> frag LDS conflict-free
//       B as [kpair=16][BN+8] uint32 (half2 of rows 2p,2p+1) -> frag LDS conflict-free
template<int BM, int BN, int WM, int WN, typename AT, typename CT>
__global__ __launch_bounds__((BM / WM) * (BN / WN) * 32)
void h16gemm(const AT* __restrict__ A, const float* __restrict__ B,
             const float* __restrict__ bias, CT* __restrict__ C,
             int M, int N, int K, int relu)
{
    constexpr bool AH = std::is_same_v<AT, __half>;
    constexpr bool CH = std::is_same_v<CT, __half>;
    constexpr int BK = 32;
    constexpr int WARPS = (BM / WM) * (BN / WN);
    constexpr int THREADS = WARPS * 32;
    constexpr int MF = WM / 16, NF = WN / 8;
    constexpr int AST  = 20;        // uint32 stride per A row
    constexpr int BSTn = BN + 8;    // uint32 stride per B k-pair row
    constexpr int ALD = (BM * BK) / (4 * THREADS);       // 4-elem units/thread (A)
    constexpr int BLD = ((BK / 2) * (BN / 4)) / THREADS; // transpose units/thread
    constexpr int STAGE = BM * AST + (BK / 2) * BSTn;    // uint32

    extern __shared__ uint32_t smem_dyn[];
    const int tid = threadIdx.x;
    const int wid = tid >> 5, lane = tid & 31;
    const int wm = wid / (BN / WN), wn = wid % (BN / WN);
    const int g = lane >> 2, tg = lane & 3;
    const int row0 = blockIdx.y * BM, col0 = blockIdx.x * BN;

    float acc[MF][NF][4];
    #pragma unroll
    for (int i = 0; i < MF; i++)
        #pragma unroll
        for (int j = 0; j < NF; j++)
            #pragma unroll
            for (int q = 0; q < 4; q++) acc[i][j][q] = 0.f;

    float4 pa[AH ? 1 : ALD];
    uint2  pah[AH ? ALD : 1];
    float4 pb[BLD][2];
    auto ldAB = [&](int k0) {
        #pragma unroll
        for (int j = 0; j < ALD; j++) {
            int fid = tid + j * THREADS;
            int r = fid >> 3, c4 = fid & 7;           // 8 4-elem units per 32-elem row
            if constexpr (AH) {
                pah[j] = *reinterpret_cast<const uint2*>(
                    A + (size_t)(row0 + r) * K + k0 + c4 * 4);
            } else {
                pa[j] = *reinterpret_cast<const float4*>(
                    A + (size_t)(row0 + r) * K + k0 + c4 * 4);
            }
        }
        #pragma unroll
        for (int j = 0; j < BLD; j++) {
            int fid = tid + j * THREADS;
            int n = fid % (BN / 4), p = fid / (BN / 4);
            pb[j][0] = *reinterpret_cast<const float4*>(
                B + (size_t)(k0 + 2 * p    ) * N + col0 + 4 * n);
            pb[j][1] = *reinterpret_cast<const float4*>(
                B + (size_t)(k0 + 2 * p + 1) * N + col0 + 4 * n);
        }
    };
    auto stash = [&](int buf) {
        uint32_t* As = smem_dyn + buf * STAGE;
        uint32_t* Bs = As + BM * AST;
        #pragma unroll
        for (int j = 0; j < ALD; j++) {
            int fid = tid + j * THREADS;
            int r = fid >> 3, c4 = fid & 7;
            uint2 w;
            if constexpr (AH) {
                w = pah[j];
            } else {
                w.x = f2h2(pa[j].x, pa[j].y);
                w.y = f2h2(pa[j].z, pa[j].w);
            }
            *reinterpret_cast<uint2*>(&As[r * AST + c4 * 2]) = w;
        }
        #pragma unroll
        for (int j = 0; j < BLD; j++) {
            int fid = tid + j * THREADS;
            int n = fid % (BN / 4), p = fid / (BN / 4);
            uint4 w;
            w.x = f2h2(pb[j][0].x, pb[j][1].x);
            w.y = f2h2(pb[j][0].y, pb[j][1].y);
            w.z = f2h2(pb[j][0].z, pb[j][1].z);
            w.w = f2h2(pb[j][0].w, pb[j][1].w);
            *reinterpret_cast<uint4*>(&Bs[p * BSTn + 4 * n]) = w;
        }
    };

    ldAB(0);
    stash(0);
    __syncthreads();

    const int niter = K / BK;
    for (int it = 0; it < niter; ++it) {
        const int cur = it & 1;
        if (it + 1 < niter) ldAB((it + 1) * BK);
        const uint32_t* As = smem_dyn + cur * STAGE;
        const uint32_t* Bs = As + BM * AST;
        #pragma unroll
        for (int kk = 0; kk < 2; kk++) {            // two k16 steps per BK=32
            uint32_t af[MF][4], bf[NF][2];
            #pragma unroll
            for (int mf = 0; mf < MF; mf++) {
                int r = wm * WM + mf * 16;
                af[mf][0] = As[(r + g    ) * AST + kk * 8 + tg    ];
                af[mf][1] = As[(r + g + 8) * AST + kk * 8 + tg    ];
                af[mf][2] = As[(r + g    ) * AST + kk * 8 + tg + 4];
                af[mf][3] = As[(r + g + 8) * AST + kk * 8 + tg + 4];
            }
            #pragma unroll
            for (int nf = 0; nf < NF; nf++) {
                int c = wn * WN + nf * 8 + g;
                bf[nf][0] = Bs[(kk * 8 + tg    ) * BSTn + c];
                bf[nf][1] = Bs[(kk * 8 + tg + 4) * BSTn + c];
            }
            #pragma unroll
            for (int mf = 0; mf < MF; mf++)
                #pragma unroll
                for (int nf = 0; nf < NF; nf++)
                    asm volatile(
                        "mma.sync.aligned.m16n8k16.row.col.f32.f16.f16.f32 "
                        "{%0,%1,%2,%3},{%4,%5,%6,%7},{%8,%9},{%0,%1,%2,%3};\n"
                        : "+f"(acc[mf][nf][0]), "+f"(acc[mf][nf][1]),
                          "+f"(acc[mf][nf][2]), "+f"(acc[mf][nf][3])
                        : "r"(af[mf][0]), "r"(af[mf][1]),
                          "r"(af[mf][2]), "r"(af[mf][3]),
                          "r"(bf[nf][0]), "r"(bf[nf][1]));
        }
        if (it + 1 < niter) {
            stash(1 - cur);
            __syncthreads();
        }
    }
    #pragma unroll
    for (int mf = 0; mf < MF; mf++) {
        int r = row0 + wm * WM + mf * 16 + g;
        #pragma unroll
        for (int nf = 0; nf < NF; nf++) {
            int c = col0 + wn * WN + nf * 8 + tg * 2;
            float b0v = bias ? bias[c] : 0.f;
            float b1v = bias ? bias[c + 1] : 0.f;
            float v0 = acc[mf][nf][0] + b0v, v1 = acc[mf][nf][1] + b1v;
            float v2 = acc[mf][nf][2] + b0v, v3 = acc[mf][nf][3] + b1v;
            if (relu) {
                v0 = fmaxf(v0, 0.f); v1 = fmaxf(v1, 0.f);
                v2 = fmaxf(v2, 0.f); v3 = fmaxf(v3, 0.f);
            }
            if constexpr (CH) {
                *reinterpret_cast<uint32_t*>(C + (size_t)r * N + c)       = f2h2(v0, v1);
                *reinterpret_cast<uint32_t*>(C + (size_t)(r + 8) * N + c) = f2h2(v2, v3);
            } else {
                *reinterpret_cast<float2*>(C + (size_t)r * N + c)       = make_float2(v0, v1);
                *reinterpret_cast<float2*>(C + (size_t)(r + 8) * N + c) = make_float2(v2, v3);
            }
        }
    }
}

// ---------------- fp32 tiled SGEMM (tail GEMM only) --------------------------
template<int BM, int BN, int BK, int TM, int TN>
__global__ __launch_bounds__((BM / TM) * (BN / TN))
void sgemm(const float* __restrict__ A, const float* __restrict__ B,
           const float* __restrict__ bias, float* __restrict__ C,
           int M, int N, int K, int relu)
{
    constexpr int THREADS = (BM / TM) * (BN / TN);
    __shared__ float As[BK][BM];
    __shared__ float Bs[BK][BN];
    const int tid = threadIdx.x;
    const int row0 = blockIdx.y * BM, col0 = blockIdx.x * BN;
    const int tr = (tid / (BN / TN)) * TM;
    const int tc = (tid % (BN / TN)) * TN;
    const bool vb = (N % 4) == 0;

    float acc[TM][TN];
    #pragma unroll
    for (int i = 0; i < TM; i++)
        #pragma unroll
        for (int j = 0; j < TN; j++) acc[i][j] = 0.f;

    for (int k0 = 0; k0 < K; k0 += BK) {
        #pragma unroll 4
        for (int i = tid * 4; i < BM * BK; i += THREADS * 4) {
            int r = i / BK, c = i % BK;
            int gr = row0 + r, gc = k0 + c;
            float4 v = make_float4(0.f, 0.f, 0.f, 0.f);
            if (gr < M) v = *reinterpret_cast<const float4*>(A + (size_t)gr * K + gc);
            As[c + 0][r] = v.x; As[c + 1][r] = v.y;
            As[c + 2][r] = v.z; As[c + 3][r] = v.w;
        }
        #pragma unroll 4
        for (int i = tid * 4; i < BK * BN; i += THREADS * 4) {
            int r = i / BN, c = i % BN;
            int gr = k0 + r, gc = col0 + c;
            float vv0 = 0.f, vv1 = 0.f, vv2 = 0.f, vv3 = 0.f;
            if (vb && gc + 3 < N) {
                float4 v = *reinterpret_cast<const float4*>(B + (size_t)gr * N + gc);
                vv0 = v.x; vv1 = v.y; vv2 = v.z; vv3 = v.w;
            } else {
                if (gc + 0 < N) vv0 = B[(size_t)gr * N + gc + 0];
                if (gc + 1 < N) vv1 = B[(size_t)gr * N + gc + 1];
                if (gc + 2 < N) vv2 = B[(size_t)gr * N + gc + 2];
                if (gc + 3 < N) vv3 = B[(size_t)gr * N + gc + 3];
            }
            Bs[r][c + 0] = vv0; Bs[r][c + 1] = vv1;
            Bs[r][c + 2] = vv2; Bs[r][c + 3] = vv3;
        }
        __syncthreads();
        #pragma unroll
        for (int kk = 0; kk < BK; kk++) {
            float ar[TM], br[TN];
            #pragma unroll
            for (int i = 0; i < TM; i++) ar[i] = As[kk][tr + i];
            #pragma unroll
            for (int j = 0; j < TN; j++) br[j] = Bs[kk][tc + j];
            #pragma unroll
            for (int i = 0; i < TM; i++)
                #pragma unroll
                for (int j = 0; j < TN; j++) acc[i][j] += ar[i] * br[j];
        }
        __syncthreads();
    }
    #pragma unroll
    for (int i = 0; i < TM; i++) {
        int r = row0 + tr + i;
        if (r >= M) continue;
        #pragma unroll
        for (int j = 0; j < TN; j++) {
            int c = col0 + tc + j;
            if (c >= N) continue;
            float v = acc[i][j] + (bias ? bias[c] : 0.f);
            if (relu) v = fmaxf(v, 0.f);
            C[(size_t)r * N + c] = v;
        }
    }
}

// ---------------- GAT layer 1 -------------------------------------------------
// wa[f][o] = sum_c W1[f][h*512+c] * a[h][c], o in [0,16): 0-7 src, 8-15 dst
__global__ void prep_wa1_kernel(const float* __restrict__ W1,
                                const float* __restrict__ a1s,
                                const float* __restrict__ a1d) {
    int f = blockIdx.x;
    int w = threadIdx.x >> 5, lane = threadIdx.x & 31;   // 16 warps
    int h = w & 7;
    const float* a = (w < 8) ? a1s : a1d;
    float s = 0.f;
    for (int c = lane; c < HID; c += 32)
        s += W1[(size_t)f * D1 + h * HID + c] * a[h * HID + c];
    s = warpSum(s);
    if (lane == 0) g_wa1[f * 16 + w] = s;
}

// alpha_src/dst[n][h] = x[n,:] @ wa1[:, h]   (exact linear-algebra fusion)
__global__ void alpha1_fast_kernel(const float* __restrict__ x) {
    int n = blockIdx.x * 8 + (threadIdx.x >> 5);
    int lane = threadIdx.x & 31;
    float xv[4];
    #pragma unroll
    for (int j = 0; j < 4; j++) xv[j] = x[(size_t)n * F_IN + lane + 32 * j];
    #pragma unroll
    for (int o = 0; o < 16; o++) {
        float s = 0.f;
        #pragma unroll
        for (int j = 0; j < 4; j++) s += xv[j] * g_wa1[(lane + 32 * j) * 16 + o];
        s = warpSum(s);
        if (lane == 0) {
            if (o < 8) g_as1[n * 8 + o] = s;
            else       g_ad1[n * 8 + (o - 8)] = s;
        }
    }
}

// fused leaky-relu logits + segment-softmax + weighted gather-aggregate (L1)
#define CH1 128
__global__ __launch_bounds__(256)
void norm_agg1_kernel(const float* __restrict__ b1) {
    __shared__ float sm[HEADS], sinv[HEADS], sadn[HEADS];
    __shared__ float sal[CH1 * HEADS];
    __shared__ int   ssrc[CH1];
    int n = blockIdx.x;
    int t = threadIdx.x, w = t >> 5, lane = t & 31;   // warp w = head w
    int beg = g_off[n], end = g_off[n + 1];

    float adn = g_ad1[n * HEADS + w];
    if (lane == 0) sadn[w] = adn;
    float m = -3.4e38f;
    for (int i = beg + lane; i < end; i += 32)
        m = fmaxf(m, lrelu(g_as1[g_esrc[i] * HEADS + w] + adn));
    m = warpMax(m);
    float s = 0.f;
    for (int i = beg + lane; i < end; i += 32)
        s += expf(lrelu(g_as1[g_esrc[i] * HEADS + w] + adn) - m);
    s = warpSum(s);
    if (lane == 0) { sm[w] = m; sinv[w] = 1.f / s; }
    __syncthreads();

    int c0 = t * 16;
    int head = c0 >> 9;
    float acc[16];
    #pragma unroll
    for (int j = 0; j < 16; j++) acc[j] = 0.f;

    for (int cs = beg; cs < end; cs += CH1) {
        int cnt = min(end - cs, CH1);
        for (int j = t; j < cnt; j += 256) ssrc[j] = g_esrc[cs + j];
        __syncthreads();
        for (int j = t; j < cnt * HEADS; j += 256) {
            int i = j >> 3, h = j & 7;
            float v = lrelu(g_as1[ssrc[i] * HEADS + h] + sadn[h]);
            sal[j] = expf(v - sm[h]) * sinv[h];
        }
        __syncthreads();
        #pragma unroll 2
        for (int i = 0; i < cnt; i++) {
            float al = sal[i * HEADS + head];
            const uint4* hs = reinterpret_cast<const uint4*>(
                g_h1 + (size_t)ssrc[i] * D1 + c0);        // 16 halves = 2 uint4
            uint4 u0 = hs[0], u1 = hs[1];
            float2 f;
            f = h2f2(u0.x); acc[0]  += f.x * al; acc[1]  += f.y * al;
            f = h2f2(u0.y); acc[2]  += f.x * al; acc[3]  += f.y * al;
            f = h2f2(u0.z); acc[4]  += f.x * al; acc[5]  += f.y * al;
            f = h2f2(u0.w); acc[6]  += f.x * al; acc[7]  += f.y * al;
            f = h2f2(u1.x); acc[8]  += f.x * al; acc[9]  += f.y * al;
            f = h2f2(u1.y); acc[10] += f.x * al; acc[11] += f.y * al;
            f = h2f2(u1.z); acc[12] += f.x * al; acc[13] += f.y * al;
            f = h2f2(u1.w); acc[14] += f.x * al; acc[15] += f.y * al;
        }
        __syncthreads();
    }
    // relu + fp16 store (out1 feeds GEMM2 which converts to fp16 anyway)
    uint4 w0, w1;
    float r0, r1;
    r0 = fmaxf(acc[0]  + b1[c0 + 0],  0.f); r1 = fmaxf(acc[1]  + b1[c0 + 1],  0.f); w0.x = f2h2(r0, r1);
    r0 = fmaxf(acc[2]  + b1[c0 + 2],  0.f); r1 = fmaxf(acc[3]  + b1[c0 + 3],  0.f); w0.y = f2h2(r0, r1);
    r0 = fmaxf(acc[4]  + b1[c0 + 4],  0.f); r1 = fmaxf(acc[5]  + b1[c0 + 5],  0.f); w0.z = f2h2(r0, r1);
    r0 = fmaxf(acc[6]  + b1[c0 + 6],  0.f); r1 = fmaxf(acc[7]  + b1[c0 + 7],  0.f); w0.w = f2h2(r0, r1);
    r0 = fmaxf(acc[8]  + b1[c0 + 8],  0.f); r1 = fmaxf(acc[9]  + b1[c0 + 9],  0.f); w1.x = f2h2(r0, r1);
    r0 = fmaxf(acc[10] + b1[c0 + 10], 0.f); r1 = fmaxf(acc[11] + b1[c0 + 11], 0.f); w1.y = f2h2(r0, r1);
    r0 = fmaxf(acc[12] + b1[c0 + 12], 0.f); r1 = fmaxf(acc[13] + b1[c0 + 13], 0.f); w1.z = f2h2(r0, r1);
    r0 = fmaxf(acc[14] + b1[c0 + 14], 0.f); r1 = fmaxf(acc[15] + b1[c0 + 15], 0.f); w1.w = f2h2(r0, r1);
    uint4* o = reinterpret_cast<uint4*>(g_out1 + (size_t)n * D1 + c0);
    o[0] = w0; o[1] = w1;
}

// ---------------- GAT layer 2 -------------------------------------------------
__global__ void alpha2_kernel(const float* __restrict__ asrc,
                              const float* __restrict__ adst) {
    int n = blockIdx.x * 8 + (threadIdx.x >> 5);
    int lane = threadIdx.x & 31;
    const __half* hrow = g_h2 + (size_t)n * HID;
    float s1 = 0.f, s2 = 0.f;
    for (int c = lane * 2; c < HID; c += 64) {
        float2 v = h2f2(*reinterpret_cast<const uint32_t*>(hrow + c));
        s1 += v.x * asrc[c] + v.y * asrc[c + 1];
        s2 += v.x * adst[c] + v.y * adst[c + 1];
    }
    s1 = warpSum(s1); s2 = warpSum(s2);
    if (lane == 0) { g_as2[n] = s1; g_ad2[n] = s2; }
}

// fused leaky-relu logits + segment-softmax + aggregate (L2)
#define CH2 256
__global__ __launch_bounds__(128)
void norm_agg2_kernel(const float* __restrict__ b2) {
    __shared__ float sred[4];
    __shared__ float sal[CH2];
    __shared__ int   ssrc[CH2];
    int n = blockIdx.x;
    int t = threadIdx.x, w = t >> 5, lane = t & 31;
    int beg = g_off[n], end = g_off[n + 1];
    float adn = g_ad2[n];

    float m = -3.4e38f;
    for (int i = beg + t; i < end; i += 128)
        m = fmaxf(m, lrelu(g_as2[g_esrc[i]] + adn));
    m = warpMax(m);
    if (lane == 0) sred[w] = m;
    __syncthreads();
    m = fmaxf(fmaxf(sred[0], sred[1]), fmaxf(sred[2], sred[3]));
    __syncthreads();
    float s = 0.f;
    for (int i = beg + t; i < end; i += 128)
        s += expf(lrelu(g_as2[g_esrc[i]] + adn) - m);
    s = warpSum(s);
    if (lane == 0) sred[w] = s;
    __syncthreads();
    float inv = 1.f / (sred[0] + sred[1] + sred[2] + sred[3]);

    int c0 = t * 4;
    float a0 = 0.f, a1 = 0.f, a2 = 0.f, a3 = 0.f;
    for (int cs = beg; cs < end; cs += CH2) {
        int cnt = min(end - cs, CH2);
        __syncthreads();
        for (int j = t; j < cnt; j += 128) {
            int sc = g_esrc[cs + j];
            ssrc[j] = sc;
            sal[j] = expf(lrelu(g_as2[sc] + adn) - m) * inv;
        }
        __syncthreads();
        #pragma unroll 2
        for (int i = 0; i < cnt; i++) {
            float al = sal[i];
            uint2 u = *reinterpret_cast<const uint2*>(
                g_h2 + (size_t)ssrc[i] * HID + c0);       // 4 halves
            float2 f0 = h2f2(u.x), f1 = h2f2(u.y);
            a0 += f0.x * al; a1 += f0.y * al;
            a2 += f1.x * al; a3 += f1.y * al;
        }
    }
    float v0 = fmaxf(a0 + b2[c0 + 0], 0.f);
    float v1 = fmaxf(a1 + b2[c0 + 1], 0.f);
    float v2 = fmaxf(a2 + b2[c0 + 2], 0.f);
    float v3 = fmaxf(a3 + b2[c0 + 3], 0.f);
    uint2 w2;
    w2.x = f2h2(v0, v1);
    w2.y = f2h2(v2, v3);
    *reinterpret_cast<uint2*>(g_out2 + (size_t)n * HID + c0) = w2;
}

// ---------------- launch -----------------------------------------------------
// STAGE(BM, BN) = BM*20 + 16*(BN+8) uint32, double-buffered, in bytes
static inline int h16_smem_bytes(int BM, int BN) {
    return 2 * (BM * 20 + 16 * (BN + 8)) * 4;
}

extern "C" void kernel_launch(void* const* d_in, const int* in_sizes, int n_in,
                              void* d_out, int out_size) {
    const float* x      = (const float*)d_in[0];
    const int*   ei     = (const int*)d_in[1];
    const float* W1     = (const float*)d_in[3];
    const float* a_src1 = (const float*)d_in[4];
    const float* a_dst1 = (const float*)d_in[5];
    const float* b1     = (const float*)d_in[6];
    const float* W2     = (const float*)d_in[7];
    const float* a_src2 = (const float*)d_in[8];
    const float* a_dst2 = (const float*)d_in[9];
    const float* b2     = (const float*)d_in[10];
    const float* fc1w   = (const float*)d_in[11];
    const float* fc1b   = (const float*)d_in[12];
    const float* fc2w   = (const float*)d_in[13];
    const float* fc2b   = (const float*)d_in[14];
    const float* fc3w   = (const float*)d_in[15];
    const float* fc3b   = (const float*)d_in[16];
    float* out = (float*)d_out;

    __half *h1, *o1, *h2, *o2, *gg1;
    float *gg2;
    cudaGetSymbolAddress((void**)&h1,  g_h1);
    cudaGetSymbolAddress((void**)&o1,  g_out1);
    cudaGetSymbolAddress((void**)&h2,  g_h2);
    cudaGetSymbolAddress((void**)&o2,  g_out2);
    cudaGetSymbolAddress((void**)&gg1, g_g1);
    cudaGetSymbolAddress((void**)&gg2, g_g2);

    const int SM_BIG   = h16_smem_bytes(128, 128);   // 37888 B
    const int SM_SMALL = h16_smem_bytes(64, 64);     // 19456 B
    cudaFuncSetAttribute((const void*)h16gemm<128, 128, 64, 32, float, __half>,
                         cudaFuncAttributeMaxDynamicSharedMemorySize, SM_BIG);
    cudaFuncSetAttribute((const void*)h16gemm<128, 128, 64, 32, __half, __half>,
                         cudaFuncAttributeMaxDynamicSharedMemorySize, SM_BIG);
    cudaFuncSetAttribute((const void*)h16gemm<64, 64, 32, 32, __half, __half>,
                         cudaFuncAttributeMaxDynamicSharedMemorySize, SM_SMALL);
    cudaFuncSetAttribute((const void*)h16gemm<64, 64, 32, 32, __half, float>,
                         cudaFuncAttributeMaxDynamicSharedMemorySize, SM_SMALL);

    // alpha projection + CSR head (input-only deps)
    prep_wa1_kernel<<<F_IN, 512>>>(W1, a_src1, a_dst1);
    alpha1_fast_kernel<<<NN / 8, 256>>>(x);
    detect_init_kernel<<<(NN + 255) / 256, 256>>>(ei);
    count_kernel<<<(ET + 255) / 256, 256>>>(ei);
    scan_kernel<<<1, 1024>>>();

    // GAT layer 1 GEMM h1 = x @ W1 (FP16 tensor cores, fp32 accum, fp16 out)
    h16gemm<128, 128, 64, 32, float, __half>
        <<<dim3(D1 / 128, NN / 128), 256, SM_BIG>>>(
        x, W1, nullptr, h1, NN, D1, F_IN, 0);

    // CSR fill (needed only by norm_agg1)
    fill_kernel<<<(ET + 255) / 256, 256>>>(ei);
    norm_agg1_kernel<<<NN, 256>>>(b1);

    // GAT layer 2: h2 = out1 @ W2 (fp16 A operand, fp16 out)
    h16gemm<128, 128, 64, 32, __half, __half>
        <<<dim3(HID / 128, NN / 128), 256, SM_BIG>>>(
        o1, W2, nullptr, h2, NN, HID, D1, 0);
    alpha2_kernel<<<NN / 8, 256>>>(a_src2, a_dst2);
    norm_agg2_kernel<<<NN, 128>>>(b2);

    // MLP head: g = out2 viewed as [512, 4096]
    h16gemm<64, 64, 32, 32, __half, __half>
        <<<dim3(512 / 64, 512 / 64), 128, SM_SMALL>>>(
        o2, fc1w, fc1b, gg1, 512, 512, D1, 1);
    h16gemm<64, 64, 32, 32, __half, float>
        <<<dim3(128 / 64, 512 / 64), 128, SM_SMALL>>>(
        gg1, fc2w, fc2b, gg2, 512, 128, 512, 1);
    sgemm<64, 64, 16, 4, 4><<<dim3(1, 512 / 64), 256>>>(
        gg2, fc3w, fc3b, out, 512, 10, 128, 0);
}

// round 16
// speedup vs baseline: 2.3226x; 1.0702x over previous
#include <cuda_runtime.h>
#include <cuda_fp16.h>
#include <cstdint>
#include <type_traits>

#define NN   4096
#define NE   32768
#define ET   (NE + NN)        // edges + self loops = 36864
#define F_IN 128
#define HEADS 8
#define HID  512
#define D1   (HEADS * HID)    // 4096

// ---------------- scratch (device globals; no allocation allowed) ----------
__device__ __half g_h1[(size_t)NN * D1];     // 32 MB (fp16)
__device__ __half g_out1[(size_t)NN * D1];   // 32 MB (fp16)
__device__ __half g_h2[NN * HID];            // 4 MB
__device__ __half g_out2[NN * HID];          // 4 MB
__device__ __half g_g1[512 * 512];
__device__ float  g_g2[512 * 128];
__device__ __half g_w1h[F_IN * D1];          // fp16 copies of weights
__device__ __half g_w2h[(size_t)D1 * HID];
__device__ __half g_f1h[(size_t)D1 * HID];
__device__ __half g_f2h[HID * 128];
__device__ float g_wa1[F_IN * 16];           // W1 @ [a_src;a_dst] projections
__device__ float g_as1[NN * HEADS], g_ad1[NN * HEADS];
__device__ float g_as2[NN], g_ad2[NN];
__device__ int   g_deg[NN], g_cur[NN], g_off[NN + 1];
__device__ int   g_esrc[ET];
__device__ int   g_is64;

// ---------------- helpers ---------------------------------------------------
__device__ __forceinline__ float warpSum(float v) {
    #pragma unroll
    for (int o = 16; o; o >>= 1) v += __shfl_xor_sync(0xffffffffu, v, o);
    return v;
}
__device__ __forceinline__ float warpMax(float v) {
    #pragma unroll
    for (int o = 16; o; o >>= 1) v = fmaxf(v, __shfl_xor_sync(0xffffffffu, v, o));
    return v;
}
// pack two fp32 into fp16x2: low half = lo, high half = hi
__device__ __forceinline__ uint32_t f2h2(float lo, float hi) {
    uint32_t r;
    asm("cvt.rn.f16x2.f32 %0, %1, %2;" : "=r"(r) : "f"(hi), "f"(lo));
    return r;
}
// unpack fp16x2 -> float2
__device__ __forceinline__ float2 h2f2(uint32_t u) {
    return __half22float2(*reinterpret_cast<const __half2*>(&u));
}
__device__ __forceinline__ float lrelu(float v) {
    return v > 0.f ? v : 0.2f * v;
}
// edge_index may be int64 or int32 depending on JAX x64 config; g_is64 set at runtime.
__device__ __forceinline__ int eload(const int* ei, int pos) {
    return g_is64 ? ei[2 * pos] : ei[pos];
}
__device__ __forceinline__ int esrc_of(const int* ei, int e) {
    return (e < NE) ? eload(ei, e) : (e - NE);
}
__device__ __forceinline__ int edst_of(const int* ei, int e) {
    return (e < NE) ? eload(ei, NE + e) : (e - NE);
}

// ---------------- weight fp32 -> fp16 conversion (one pass) ------------------
#define N1 (F_IN * D1 / 4)
#define N2 (D1 * HID / 4)
#define N3 (D1 * HID / 4)
#define N4 (HID * 128 / 4)
#define NTOT (N1 + N2 + N3 + N4)
__global__ void cvt_weights_kernel(const float* __restrict__ W1,
                                   const float* __restrict__ W2,
                                   const float* __restrict__ F1,
                                   const float* __restrict__ F2) {
    int i = blockIdx.x * blockDim.x + threadIdx.x;   // float4 index
    if (i >= NTOT) return;
    const float* src; __half* dst; int o;
    if (i < N1)                { src = W1; dst = g_w1h; o = i; }
    else if (i < N1 + N2)      { src = W2; dst = g_w2h; o = i - N1; }
    else if (i < N1 + N2 + N3) { src = F1; dst = g_f1h; o = i - N1 - N2; }
    else                       { src = F2; dst = g_f2h; o = i - N1 - N2 - N3; }
    float4 v = reinterpret_cast<const float4*>(src)[o];
    uint2 w;
    w.x = f2h2(v.x, v.y);
    w.y = f2h2(v.z, v.w);
    reinterpret_cast<uint2*>(dst)[o] = w;
}

// ---------------- dtype sniff + CSR build ----------------------------------
__global__ void detect_init_kernel(const int* __restrict__ ei) {
    int i = blockIdx.x * blockDim.x + threadIdx.x;
    if (i == 0) {
        int all0 = 1;
        for (int k = 1; k < 64; k += 2) all0 &= (ei[k] == 0);
        g_is64 = all0;
    }
    if (i < NN) { g_deg[i] = 0; g_cur[i] = 0; }
}

__global__ void count_kernel(const int* __restrict__ ei) {
    int e = blockIdx.x * blockDim.x + threadIdx.x;
    if (e >= ET) return;
    atomicAdd(&g_deg[edst_of(ei, e)], 1);
}

__global__ void scan_kernel() {
    __shared__ int ws[32];
    int t = threadIdx.x, lane = t & 31, wid = t >> 5;
    int a0 = g_deg[4 * t + 0], a1 = g_deg[4 * t + 1];
    int a2 = g_deg[4 * t + 2], a3 = g_deg[4 * t + 3];
    int tsum = a0 + a1 + a2 + a3;
    int x = tsum;
    #pragma unroll
    for (int o = 1; o < 32; o <<= 1) {
        int y = __shfl_up_sync(0xffffffffu, x, o);
        if (lane >= o) x += y;
    }
    if (lane == 31) ws[wid] = x;
    __syncthreads();
    if (wid == 0) {
        int y = ws[lane];
        #pragma unroll
        for (int o = 1; o < 32; o <<= 1) {
            int z = __shfl_up_sync(0xffffffffu, y, o);
            if (lane >= o) y += z;
        }
        ws[lane] = y;
    }
    __syncthreads();
    int base = (wid ? ws[wid - 1] : 0) + (x - tsum);
    g_off[4 * t + 0] = base;
    g_off[4 * t + 1] = base + a0;
    g_off[4 * t + 2] = base + a0 + a1;
    g_off[4 * t + 3] = base + a0 + a1 + a2;
    if (t == 1023) g_off[NN] = base + tsum;
}

__global__ void fill_kernel(const int* __restrict__ ei) {
    int e = blockIdx.x * blockDim.x + threadIdx.x;
    if (e >= ET) return;
    int s = esrc_of(ei, e), d = edst_of(ei, e);
    int p = g_off[d] + atomicAdd(&g_cur[d], 1);
    g_esrc[p] = s;
}

// ---------------- FP16 tensor-core GEMM (mma.sync m16n8k16, dbl-buffered) ----
// A[M,K] rm (fp32 or fp16), B[K,N] rm fp16, C[M,N] (fp32 or fp16).
// M%BM==0, N%BN==0, K%32==0. fp32 accumulate.
// SMEM: A as [BM][AST=20] uint32 (16 half2 k-pairs + 4 pad)  -> frag LDS conflict-free
//       B as [kpair=16][BN+8] uint32 (half2 of rows 2p,2p+1) -> frag LDS conflict-free
template<int BM, int BN, int WM, int WN, typename AT, typename CT>
__global__ __launch_bounds__((BM / WM) * (BN / WN) * 32)
void h16gemm(const AT* __restrict__ A, const __half* __restrict__ B,
             const float* __restrict__ bias, CT* __restrict__ C,
             int M, int N, int K, int relu)
{
    constexpr bool AH = std::is_same_v<AT, __half>;
    constexpr bool CH = std::is_same_v<CT, __half>;
    constexpr int BK = 32;
    constexpr int WARPS = (BM / WM) * (BN / WN);
    constexpr int THREADS = WARPS * 32;
    constexpr int MF = WM / 16, NF = WN / 8;
    constexpr int AST  = 20;        // uint32 stride per A row
    constexpr int BSTn = BN + 8;    // uint32 stride per B k-pair row
    constexpr int ALD = (BM * BK) / (4 * THREADS);       // 4-elem units/thread (A)
    constexpr int BLD = ((BK / 2) * (BN / 4)) / THREADS; // transpose units/thread
    constexpr int STAGE = BM * AST + (BK / 2) * BSTn;    // uint32

    extern __shared__ uint32_t smem_dyn[];
    const int tid = threadIdx.x;
    const int wid = tid >> 5, lane = tid & 31;
    const int wm = wid / (BN / WN), wn = wid % (BN / WN);
    const int g = lane >> 2, tg = lane & 3;
    const int row0 = blockIdx.y * BM, col0 = blockIdx.x * BN;

    float acc[MF][NF][4];
    #pragma unroll
    for (int i = 0; i < MF; i++)
        #pragma unroll
        for (int j = 0; j < NF; j++)
            #pragma unroll
            for (int q = 0; q < 4; q++) acc[i][j][q] = 0.f;

    float4 pa[AH ? 1 : ALD];
    uint2  pah[AH ? ALD : 1];
    uint2  pb[BLD][2];
    auto ldAB = [&](int k0) {
        #pragma unroll
        for (int j = 0; j < ALD; j++) {
            int fid = tid + j * THREADS;
            int r = fid >> 3, c4 = fid & 7;           // 8 4-elem units per 32-elem row
            if constexpr (AH) {
                pah[j] = *reinterpret_cast<const uint2*>(
                    A + (size_t)(row0 + r) * K + k0 + c4 * 4);
            } else {
                pa[j] = *reinterpret_cast<const float4*>(
                    A + (size_t)(row0 + r) * K + k0 + c4 * 4);
            }
        }
        #pragma unroll
        for (int j = 0; j < BLD; j++) {
            int fid = tid + j * THREADS;
            int n = fid % (BN / 4), p = fid / (BN / 4);
            pb[j][0] = *reinterpret_cast<const uint2*>(
                B + (size_t)(k0 + 2 * p    ) * N + col0 + 4 * n);
            pb[j][1] = *reinterpret_cast<const uint2*>(
                B + (size_t)(k0 + 2 * p + 1) * N + col0 + 4 * n);
        }
    };
    auto stash = [&](int buf) {
        uint32_t* As = smem_dyn + buf * STAGE;
        uint32_t* Bs = As + BM * AST;
        #pragma unroll
        for (int j = 0; j < ALD; j++) {
            int fid = tid + j * THREADS;
            int r = fid >> 3, c4 = fid & 7;
            uint2 w;
            if constexpr (AH) {
                w = pah[j];
            } else {
                w.x = f2h2(pa[j].x, pa[j].y);
                w.y = f2h2(pa[j].z, pa[j].w);
            }
            *reinterpret_cast<uint2*>(&As[r * AST + c4 * 2]) = w;
        }
        #pragma unroll
        for (int j = 0; j < BLD; j++) {
            int fid = tid + j * THREADS;
            int n = fid % (BN / 4), p = fid / (BN / 4);
            // interleave rows 2p/2p+1 per column via PRMT (no cvt needed)
            uint4 w;
            w.x = __byte_perm(pb[j][0].x, pb[j][1].x, 0x5410);
            w.y = __byte_perm(pb[j][0].x, pb[j][1].x, 0x7632);
            w.z = __byte_perm(pb[j][0].y, pb[j][1].y, 0x5410);
            w.w = __byte_perm(pb[j][0].y, pb[j][1].y, 0x7632);
            *reinterpret_cast<uint4*>(&Bs[p * BSTn + 4 * n]) = w;
        }
    };

    ldAB(0);
    stash(0);
    __syncthreads();

    const int niter = K / BK;
    for (int it = 0; it < niter; ++it) {
        const int cur = it & 1;
        if (it + 1 < niter) ldAB((it + 1) * BK);
        const uint32_t* As = smem_dyn + cur * STAGE;
        const uint32_t* Bs = As + BM * AST;
        #pragma unroll
        for (int kk = 0; kk < 2; kk++) {            // two k16 steps per BK=32
            uint32_t af[MF][4], bf[NF][2];
            #pragma unroll
            for (int mf = 0; mf < MF; mf++) {
                int r = wm * WM + mf * 16;
                af[mf][0] = As[(r + g    ) * AST + kk * 8 + tg    ];
                af[mf][1] = As[(r + g + 8) * AST + kk * 8 + tg    ];
                af[mf][2] = As[(r + g    ) * AST + kk * 8 + tg + 4];
                af[mf][3] = As[(r + g + 8) * AST + kk * 8 + tg + 4];
            }
            #pragma unroll
            for (int nf = 0; nf < NF; nf++) {
                int c = wn * WN + nf * 8 + g;
                bf[nf][0] = Bs[(kk * 8 + tg    ) * BSTn + c];
                bf[nf][1] = Bs[(kk * 8 + tg + 4) * BSTn + c];
            }
            #pragma unroll
            for (int mf = 0; mf < MF; mf++)
                #pragma unroll
                for (int nf = 0; nf < NF; nf++)
                    asm volatile(
                        "mma.sync.aligned.m16n8k16.row.col.f32.f16.f16.f32 "
                        "{%0,%1,%2,%3},{%4,%5,%6,%7},{%8,%9},{%0,%1,%2,%3};\n"
                        : "+f"(acc[mf][nf][0]), "+f"(acc[mf][nf][1]),
                          "+f"(acc[mf][nf][2]), "+f"(acc[mf][nf][3])
                        : "r"(af[mf][0]), "r"(af[mf][1]),
                          "r"(af[mf][2]), "r"(af[mf][3]),
                          "r"(bf[nf][0]), "r"(bf[nf][1]));
        }
        if (it + 1 < niter) {
            stash(1 - cur);
            __syncthreads();
        }
    }
    #pragma unroll
    for (int mf = 0; mf < MF; mf++) {
        int r = row0 + wm * WM + mf * 16 + g;
        #pragma unroll
        for (int nf = 0; nf < NF; nf++) {
            int c = col0 + wn * WN + nf * 8 + tg * 2;
            float b0v = bias ? bias[c] : 0.f;
            float b1v = bias ? bias[c + 1] : 0.f;
            float v0 = acc[mf][nf][0] + b0v, v1 = acc[mf][nf][1] + b1v;
            float v2 = acc[mf][nf][2] + b0v, v3 = acc[mf][nf][3] + b1v;
            if (relu) {
                v0 = fmaxf(v0, 0.f); v1 = fmaxf(v1, 0.f);
                v2 = fmaxf(v2, 0.f); v3 = fmaxf(v3, 0.f);
            }
            if constexpr (CH) {
                *reinterpret_cast<uint32_t*>(C + (size_t)r * N + c)       = f2h2(v0, v1);
                *reinterpret_cast<uint32_t*>(C + (size_t)(r + 8) * N + c) = f2h2(v2, v3);
            } else {
                *reinterpret_cast<float2*>(C + (size_t)r * N + c)       = make_float2(v0, v1);
                *reinterpret_cast<float2*>(C + (size_t)(r + 8) * N + c) = make_float2(v2, v3);
            }
        }
    }
}

// ---------------- fp32 tiled SGEMM (tail GEMM only) --------------------------
template<int BM, int BN, int BK, int TM, int TN>
__global__ __launch_bounds__((BM / TM) * (BN / TN))
void sgemm(const float* __restrict__ A, const float* __restrict__ B,
           const float* __restrict__ bias, float* __restrict__ C,
           int M, int N, int K, int relu)
{
    constexpr int THREADS = (BM / TM) * (BN / TN);
    __shared__ float As[BK][BM];
    __shared__ float Bs[BK][BN];
    const int tid = threadIdx.x;
    const int row0 = blockIdx.y * BM, col0 = blockIdx.x * BN;
    const int tr = (tid / (BN / TN)) * TM;
    const int tc = (tid % (BN / TN)) * TN;
    const bool vb = (N % 4) == 0;

    float acc[TM][TN];
    #pragma unroll
    for (int i = 0; i < TM; i++)
        #pragma unroll
        for (int j = 0; j < TN; j++) acc[i][j] = 0.f;

    for (int k0 = 0; k0 < K; k0 += BK) {
        #pragma unroll 4
        for (int i = tid * 4; i < BM * BK; i += THREADS * 4) {
            int r = i / BK, c = i % BK;
            int gr = row0 + r, gc = k0 + c;
            float4 v = make_float4(0.f, 0.f, 0.f, 0.f);
            if (gr < M) v = *reinterpret_cast<const float4*>(A + (size_t)gr * K + gc);
            As[c + 0][r] = v.x; As[c + 1][r] = v.y;
            As[c + 2][r] = v.z; As[c + 3][r] = v.w;
        }
        #pragma unroll 4
        for (int i = tid * 4; i < BK * BN; i += THREADS * 4) {
            int r = i / BN, c = i % BN;
            int gr = k0 + r, gc = col0 + c;
            float vv0 = 0.f, vv1 = 0.f, vv2 = 0.f, vv3 = 0.f;
            if (vb && gc + 3 < N) {
                float4 v = *reinterpret_cast<const float4*>(B + (size_t)gr * N + gc);
                vv0 = v.x; vv1 = v.y; vv2 = v.z; vv3 = v.w;
            } else {
                if (gc + 0 < N) vv0 = B[(size_t)gr * N + gc + 0];
                if (gc + 1 < N) vv1 = B[(size_t)gr * N + gc + 1];
                if (gc + 2 < N) vv2 = B[(size_t)gr * N + gc + 2];
                if (gc + 3 < N) vv3 = B[(size_t)gr * N + gc + 3];
            }
            Bs[r][c + 0] = vv0; Bs[r][c + 1] = vv1;
            Bs[r][c + 2] = vv2; Bs[r][c + 3] = vv3;
        }
        __syncthreads();
        #pragma unroll
        for (int kk = 0; kk < BK; kk++) {
            float ar[TM], br[TN];
            #pragma unroll
            for (int i = 0; i < TM; i++) ar[i] = As[kk][tr + i];
            #pragma unroll
            for (int j = 0; j < TN; j++) br[j] = Bs[kk][tc + j];
            #pragma unroll
            for (int i = 0; i < TM; i++)
                #pragma unroll
                for (int j = 0; j < TN; j++) acc[i][j] += ar[i] * br[j];
        }
        __syncthreads();
    }
    #pragma unroll
    for (int i = 0; i < TM; i++) {
        int r = row0 + tr + i;
        if (r >= M) continue;
        #pragma unroll
        for (int j = 0; j < TN; j++) {
            int c = col0 + tc + j;
            if (c >= N) continue;
            float v = acc[i][j] + (bias ? bias[c] : 0.f);
            if (relu) v = fmaxf(v, 0.f);
            C[(size_t)r * N + c] = v;
        }
    }
}

// ---------------- GAT layer 1 -------------------------------------------------
// wa[f][o] = sum_c W1[f][h*512+c] * a[h][c], o in [0,16): 0-7 src, 8-15 dst
__global__ void prep_wa1_kernel(const float* __restrict__ W1,
                                const float* __restrict__ a1s,
                                const float* __restrict__ a1d) {
    int f = blockIdx.x;
    int w = threadIdx.x >> 5, lane = threadIdx.x & 31;   // 16 warps
    int h = w & 7;
    const float* a = (w < 8) ? a1s : a1d;
    float s = 0.f;
    for (int c = lane; c < HID; c += 32)
        s += W1[(size_t)f * D1 + h * HID + c] * a[h * HID + c];
    s = warpSum(s);
    if (lane == 0) g_wa1[f * 16 + w] = s;
}

// alpha_src/dst[n][h] = x[n,:] @ wa1[:, h]   (exact linear-algebra fusion)
__global__ void alpha1_fast_kernel(const float* __restrict__ x) {
    int n = blockIdx.x * 8 + (threadIdx.x >> 5);
    int lane = threadIdx.x & 31;
    float xv[4];
    #pragma unroll
    for (int j = 0; j < 4; j++) xv[j] = x[(size_t)n * F_IN + lane + 32 * j];
    #pragma unroll
    for (int o = 0; o < 16; o++) {
        float s = 0.f;
        #pragma unroll
        for (int j = 0; j < 4; j++) s += xv[j] * g_wa1[(lane + 32 * j) * 16 + o];
        s = warpSum(s);
        if (lane == 0) {
            if (o < 8) g_as1[n * 8 + o] = s;
            else       g_ad1[n * 8 + (o - 8)] = s;
        }
    }
}

// fused leaky-relu logits + segment-softmax + weighted gather-aggregate (L1)
#define CH1 128
__global__ __launch_bounds__(256)
void norm_agg1_kernel(const float* __restrict__ b1) {
    __shared__ float sm[HEADS], sinv[HEADS], sadn[HEADS];
    __shared__ float sal[CH1 * HEADS];
    __shared__ int   ssrc[CH1];
    int n = blockIdx.x;
    int t = threadIdx.x, w = t >> 5, lane = t & 31;   // warp w = head w
    int beg = g_off[n], end = g_off[n + 1];

    float adn = g_ad1[n * HEADS + w];
    if (lane == 0) sadn[w] = adn;
    float m = -3.4e38f;
    for (int i = beg + lane; i < end; i += 32)
        m = fmaxf(m, lrelu(g_as1[g_esrc[i] * HEADS + w] + adn));
    m = warpMax(m);
    float s = 0.f;
    for (int i = beg + lane; i < end; i += 32)
        s += expf(lrelu(g_as1[g_esrc[i] * HEADS + w] + adn) - m);
    s = warpSum(s);
    if (lane == 0) { sm[w] = m; sinv[w] = 1.f / s; }
    __syncthreads();

    int c0 = t * 16;
    int head = c0 >> 9;
    float acc[16];
    #pragma unroll
    for (int j = 0; j < 16; j++) acc[j] = 0.f;

    for (int cs = beg; cs < end; cs += CH1) {
        int cnt = min(end - cs, CH1);
        for (int j = t; j < cnt; j += 256) ssrc[j] = g_esrc[cs + j];
        __syncthreads();
        for (int j = t; j < cnt * HEADS; j += 256) {
            int i = j >> 3, h = j & 7;
            float v = lrelu(g_as1[ssrc[i] * HEADS + h] + sadn[h]);
            sal[j] = expf(v - sm[h]) * sinv[h];
        }
        __syncthreads();
        #pragma unroll 2
        for (int i = 0; i < cnt; i++) {
            float al = sal[i * HEADS + head];
            const uint4* hs = reinterpret_cast<const uint4*>(
                g_h1 + (size_t)ssrc[i] * D1 + c0);        // 16 halves = 2 uint4
            uint4 u0 = hs[0], u1 = hs[1];
            float2 f;
            f = h2f2(u0.x); acc[0]  += f.x * al; acc[1]  += f.y * al;
            f = h2f2(u0.y); acc[2]  += f.x * al; acc[3]  += f.y * al;
            f = h2f2(u0.z); acc[4]  += f.x * al; acc[5]  += f.y * al;
            f = h2f2(u0.w); acc[6]  += f.x * al; acc[7]  += f.y * al;
            f = h2f2(u1.x); acc[8]  += f.x * al; acc[9]  += f.y * al;
            f = h2f2(u1.y); acc[10] += f.x * al; acc[11] += f.y * al;
            f = h2f2(u1.z); acc[12] += f.x * al; acc[13] += f.y * al;
            f = h2f2(u1.w); acc[14] += f.x * al; acc[15] += f.y * al;
        }
        __syncthreads();
    }
    // relu + fp16 store (out1 feeds GEMM2 which converts to fp16 anyway)
    uint4 w0, w1;
    float r0, r1;
    r0 = fmaxf(acc[0]  + b1[c0 + 0],  0.f); r1 = fmaxf(acc[1]  + b1[c0 + 1],  0.f); w0.x = f2h2(r0, r1);
    r0 = fmaxf(acc[2]  + b1[c0 + 2],  0.f); r1 = fmaxf(acc[3]  + b1[c0 + 3],  0.f); w0.y = f2h2(r0, r1);
    r0 = fmaxf(acc[4]  + b1[c0 + 4],  0.f); r1 = fmaxf(acc[5]  + b1[c0 + 5],  0.f); w0.z = f2h2(r0, r1);
    r0 = fmaxf(acc[6]  + b1[c0 + 6],  0.f); r1 = fmaxf(acc[7]  + b1[c0 + 7],  0.f); w0.w = f2h2(r0, r1);
    r0 = fmaxf(acc[8]  + b1[c0 + 8],  0.f); r1 = fmaxf(acc[9]  + b1[c0 + 9],  0.f); w1.x = f2h2(r0, r1);
    r0 = fmaxf(acc[10] + b1[c0 + 10], 0.f); r1 = fmaxf(acc[11] + b1[c0 + 11], 0.f); w1.y = f2h2(r0, r1);
    r0 = fmaxf(acc[12] + b1[c0 + 12], 0.f); r1 = fmaxf(acc[13] + b1[c0 + 13], 0.f); w1.z = f2h2(r0, r1);
    r0 = fmaxf(acc[14] + b1[c0 + 14], 0.f); r1 = fmaxf(acc[15] + b1[c0 + 15], 0.f); w1.w = f2h2(r0, r1);
    uint4* o = reinterpret_cast<uint4*>(g_out1 + (size_t)n * D1 + c0);
    o[0] = w0; o[1] = w1;
}

// ---------------- GAT layer 2 -------------------------------------------------
__global__ void alpha2_kernel(const float* __restrict__ asrc,
                              const float* __restrict__ adst) {
    int n = blockIdx.x * 8 + (threadIdx.x >> 5);
    int lane = threadIdx.x & 31;
    const __half* hrow = g_h2 + (size_t)n * HID;
    float s1 = 0.f, s2 = 0.f;
    for (int c = lane * 2; c < HID; c += 64) {
        float2 v = h2f2(*reinterpret_cast<const uint32_t*>(hrow + c));
        s1 += v.x * asrc[c] + v.y * asrc[c + 1];
        s2 += v.x * adst[c] + v.y * adst[c + 1];
    }
    s1 = warpSum(s1); s2 = warpSum(s2);
    if (lane == 0) { g_as2[n] = s1; g_ad2[n] = s2; }
}

// fused leaky-relu logits + segment-softmax + aggregate (L2)
#define CH2 256
__global__ __launch_bounds__(128)
void norm_agg2_kernel(const float* __restrict__ b2) {
    __shared__ float sred[4];
    __shared__ float sal[CH2];
    __shared__ int   ssrc[CH2];
    int n = blockIdx.x;
    int t = threadIdx.x, w = t >> 5, lane = t & 31;
    int beg = g_off[n], end = g_off[n + 1];
    float adn = g_ad2[n];

    float m = -3.4e38f;
    for (int i = beg + t; i < end; i += 128)
        m = fmaxf(m, lrelu(g_as2[g_esrc[i]] + adn));
    m = warpMax(m);
    if (lane == 0) sred[w] = m;
    __syncthreads();
    m = fmaxf(fmaxf(sred[0], sred[1]), fmaxf(sred[2], sred[3]));
    __syncthreads();
    float s = 0.f;
    for (int i = beg + t; i < end; i += 128)
        s += expf(lrelu(g_as2[g_esrc[i]] + adn) - m);
    s = warpSum(s);
    if (lane == 0) sred[w] = s;
    __syncthreads();
    float inv = 1.f / (sred[0] + sred[1] + sred[2] + sred[3]);

    int c0 = t * 4;
    float a0 = 0.f, a1 = 0.f, a2 = 0.f, a3 = 0.f;
    for (int cs = beg; cs < end; cs += CH2) {
        int cnt = min(end - cs, CH2);
        __syncthreads();
        for (int j = t; j < cnt; j += 128) {
            int sc = g_esrc[cs + j];
            ssrc[j] = sc;
            sal[j] = expf(lrelu(g_as2[sc] + adn) - m) * inv;
        }
        __syncthreads();
        #pragma unroll 2
        for (int i = 0; i < cnt; i++) {
            float al = sal[i];
            uint2 u = *reinterpret_cast<const uint2*>(
                g_h2 + (size_t)ssrc[i] * HID + c0);       // 4 halves
            float2 f0 = h2f2(u.x), f1 = h2f2(u.y);
            a0 += f0.x * al; a1 += f0.y * al;
            a2 += f1.x * al; a3 += f1.y * al;
        }
    }
    float v0 = fmaxf(a0 + b2[c0 + 0], 0.f);
    float v1 = fmaxf(a1 + b2[c0 + 1], 0.f);
    float v2 = fmaxf(a2 + b2[c0 + 2], 0.f);
    float v3 = fmaxf(a3 + b2[c0 + 3], 0.f);
    uint2 w2;
    w2.x = f2h2(v0, v1);
    w2.y = f2h2(v2, v3);
    *reinterpret_cast<uint2*>(g_out2 + (size_t)n * HID + c0) = w2;
}

// ---------------- launch -----------------------------------------------------
// STAGE(BM, BN) = BM*20 + 16*(BN+8) uint32, double-buffered, in bytes
static inline int h16_smem_bytes(int BM, int BN) {
    return 2 * (BM * 20 + 16 * (BN + 8)) * 4;
}

extern "C" void kernel_launch(void* const* d_in, const int* in_sizes, int n_in,
                              void* d_out, int out_size) {
    const float* x      = (const float*)d_in[0];
    const int*   ei     = (const int*)d_in[1];
    const float* W1     = (const float*)d_in[3];
    const float* a_src1 = (const float*)d_in[4];
    const float* a_dst1 = (const float*)d_in[5];
    const float* b1     = (const float*)d_in[6];
    const float* W2     = (const float*)d_in[7];
    const float* a_src2 = (const float*)d_in[8];
    const float* a_dst2 = (const float*)d_in[9];
    const float* b2     = (const float*)d_in[10];
    const float* fc1w   = (const float*)d_in[11];
    const float* fc1b   = (const float*)d_in[12];
    const float* fc2w   = (const float*)d_in[13];
    const float* fc2b   = (const float*)d_in[14];
    const float* fc3w   = (const float*)d_in[15];
    const float* fc3b   = (const float*)d_in[16];
    float* out = (float*)d_out;

    __half *h1, *o1, *h2, *o2, *gg1, *w1h, *w2h, *f1h, *f2h;
    float *gg2;
    cudaGetSymbolAddress((void**)&h1,  g_h1);
    cudaGetSymbolAddress((void**)&o1,  g_out1);
    cudaGetSymbolAddress((void**)&h2,  g_h2);
    cudaGetSymbolAddress((void**)&o2,  g_out2);
    cudaGetSymbolAddress((void**)&gg1, g_g1);
    cudaGetSymbolAddress((void**)&gg2, g_g2);
    cudaGetSymbolAddress((void**)&w1h, g_w1h);
    cudaGetSymbolAddress((void**)&w2h, g_w2h);
    cudaGetSymbolAddress((void**)&f1h, g_f1h);
    cudaGetSymbolAddress((void**)&f2h, g_f2h);

    const int SM_BIG   = h16_smem_bytes(128, 128);   // 37888 B
    const int SM_MED   = h16_smem_bytes(128, 64);    // 29696 B
    const int SM_SMALL = h16_smem_bytes(64, 64);     // 19456 B
    cudaFuncSetAttribute((const void*)h16gemm<128, 128, 64, 32, float, __half>,
                         cudaFuncAttributeMaxDynamicSharedMemorySize, SM_BIG);
    cudaFuncSetAttribute((const void*)h16gemm<128, 64, 64, 32, __half, __half>,
                         cudaFuncAttributeMaxDynamicSharedMemorySize, SM_MED);
    cudaFuncSetAttribute((const void*)h16gemm<64, 64, 32, 32, __half, __half>,
                         cudaFuncAttributeMaxDynamicSharedMemorySize, SM_SMALL);
    cudaFuncSetAttribute((const void*)h16gemm<64, 64, 32, 32, __half, float>,
                         cudaFuncAttributeMaxDynamicSharedMemorySize, SM_SMALL);

    // weights -> fp16 (same cvt.rn the GEMM stash used to apply; hoisted)
    cvt_weights_kernel<<<(NTOT + 255) / 256, 256>>>(W1, W2, fc1w, fc2w);

    // alpha projection + CSR head (input-only deps)
    prep_wa1_kernel<<<F_IN, 512>>>(W1, a_src1, a_dst1);
    alpha1_fast_kernel<<<NN / 8, 256>>>(x);
    detect_init_kernel<<<(NN + 255) / 256, 256>>>(ei);
    count_kernel<<<(ET + 255) / 256, 256>>>(ei);
    scan_kernel<<<1, 1024>>>();

    // GAT layer 1 GEMM h1 = x @ W1 (FP16 tensor cores, fp32 accum, fp16 out)
    h16gemm<128, 128, 64, 32, float, __half>
        <<<dim3(D1 / 128, NN / 128), 256, SM_BIG>>>(
        x, w1h, nullptr, h1, NN, D1, F_IN, 0);

    // CSR fill (needed only by norm_agg1)
    fill_kernel<<<(ET + 255) / 256, 256>>>(ei);
    norm_agg1_kernel<<<NN, 256>>>(b1);

    // GAT layer 2: h2 = out1 @ W2 (128x64 tiles -> 256 CTAs, full SM coverage)
    h16gemm<128, 64, 64, 32, __half, __half>
        <<<dim3(HID / 64, NN / 128), 128, SM_MED>>>(
        o1, w2h, nullptr, h2, NN, HID, D1, 0);
    alpha2_kernel<<<NN / 8, 256>>>(a_src2, a_dst2);
    norm_agg2_kernel<<<NN, 128>>>(b2);

    // MLP head: g = out2 viewed as [512, 4096]
    h16gemm<64, 64, 32, 32, __half, __half>
        <<<dim3(512 / 64, 512 / 64), 128, SM_SMALL>>>(
        o2, f1h, fc1b, gg1, 512, 512, D1, 1);
    h16gemm<64, 64, 32, 32, __half, float>
        <<<dim3(128 / 64, 512 / 64), 128, SM_SMALL>>>(
        gg1, f2h, fc2b, gg2, 512, 128, 512, 1);
    sgemm<64, 64, 16, 4, 4><<<dim3(1, 512 / 64), 256>>>(
        gg2, fc3w, fc3b, out, 512, 10, 128, 0);
}